// round 1
// baseline (speedup 1.0000x reference)
#include <cuda_runtime.h>
#include <cuda_fp16.h>

// Problem constants (shapes are fixed by the dataset)
#define Bb   2
#define Ss   256
#define Ee   64
#define HWp  1024      // H*W = 32*32
#define CHh  4
#define NHh  16        // heads per batch = (XH*YH)*CH
#define BHh  32        // Bb*NHh
#define Dd   4096      // hd*hh*ww = 16*16*16

// -------------------- scratch (device globals; no allocation) --------------------
__device__ __half g_q[(size_t)BHh * Ss * Dd];      // 64 MB
__device__ __half g_k[(size_t)BHh * Ss * Dd];      // 64 MB
__device__ __half g_v[(size_t)BHh * Ss * Dd];      // 64 MB
__device__ float  g_scores[(size_t)BHh * Ss * Ss]; // 8 MB
__device__ __half g_attn[(size_t)BHh * Ss * Ss];   // 4 MB
__device__ __half g_sa[(size_t)BHh * Ss * Dd];     // 64 MB

// ==================================================================================
// Kernel 1: QKV projection + decompose2d scatter into [b, head, s, d] fp16 layout
//   grid: (B*S, 8)  block: 256  dyn smem: 80 KB
//   qkv[o] = sum_e w_qkv[o][e] * seq[b,s,e,h,w]; o = split*64 + ch*16 + dc
//   head = (sx*2+sy)*4 + ch ; d = dc*256 + i*16 + j  (h = sx*16+i, w = sy*16+j)
// ==================================================================================
__global__ __launch_bounds__(256) void qkv_kernel(const float* __restrict__ seq,
                                                  const float* __restrict__ w_qkv) {
    extern __shared__ float sm1[];
    float* xs = sm1;              // [64][128]  channel x position
    float* wT = sm1 + 64 * 128;   // [64][192]  wT[e][o] = w_qkv[o][e]

    const int bs    = blockIdx.x;        // b*S + s
    const int chunk = blockIdx.y;        // 0..7 (128 positions each)
    const int tid   = threadIdx.x;
    const int p0    = chunk * 128;

    const float* src = seq + (size_t)bs * Ee * HWp + p0;
#pragma unroll
    for (int i = 0; i < 32; i++) {
        int idx = tid + i * 256;         // 0..8191
        int e = idx >> 7, p = idx & 127;
        xs[idx] = src[(size_t)e * HWp + p];
    }
#pragma unroll
    for (int i = 0; i < 48; i++) {
        int idx = tid + i * 256;         // 0..12287
        int o = idx % 192, e = idx / 192;
        wT[e * 192 + o] = w_qkv[o * 64 + e];
    }
    __syncthreads();

    const int tx = tid & 31;             // position lane (p = p0 + tx + 32*i)
    const int ty = tid >> 5;             // 0..7, output sub-group

    float acc[6][4][4];
#pragma unroll
    for (int r = 0; r < 6; r++)
#pragma unroll
        for (int i = 0; i < 4; i++)
#pragma unroll
            for (int j = 0; j < 4; j++) acc[r][i][j] = 0.f;

    for (int e = 0; e < 64; e++) {
        float xv[4];
#pragma unroll
        for (int i = 0; i < 4; i++) xv[i] = xs[e * 128 + tx + 32 * i];
        const float* wrow = wT + e * 192;
#pragma unroll
        for (int r = 0; r < 6; r++) {
            float4 w4 = *(const float4*)(wrow + r * 32 + ty * 4);
#pragma unroll
            for (int i = 0; i < 4; i++) {
                acc[r][i][0] = fmaf(xv[i], w4.x, acc[r][i][0]);
                acc[r][i][1] = fmaf(xv[i], w4.y, acc[r][i][1]);
                acc[r][i][2] = fmaf(xv[i], w4.z, acc[r][i][2]);
                acc[r][i][3] = fmaf(xv[i], w4.w, acc[r][i][3]);
            }
        }
    }

    const int b = bs >> 8, s = bs & 255;
#pragma unroll
    for (int r = 0; r < 6; r++) {
#pragma unroll
        for (int j = 0; j < 4; j++) {
            int o  = r * 32 + ty * 4 + j;      // 0..191
            int sp = o >> 6;                    // split 0/1/2
            int ch = (o >> 4) & 3;
            int dc = o & 15;
            __half* dst = (sp == 0) ? g_q : (sp == 1) ? g_k : g_v;
#pragma unroll
            for (int i = 0; i < 4; i++) {
                int p  = p0 + tx + 32 * i;
                int h  = p >> 5, w = p & 31;
                int sx = h >> 4, ii = h & 15;
                int sy = w >> 4, jj = w & 15;
                int head = (sx * 2 + sy) * 4 + ch;
                size_t di = ((size_t)(b * NHh + head) * Ss + s) * Dd
                          + dc * 256 + ii * 16 + jj;
                dst[di] = __float2half(acc[r][i][j]);
            }
        }
    }
}

// ==================================================================================
// Kernel 2: scores = Q @ K^T  (per head: 256x256, K=4096), fp16 in, fp32 accum
//   grid: (BH, 2, 2)  block: 256 (16x16 threads, 8x8 per thread -> 128x128 tile)
// ==================================================================================
__global__ __launch_bounds__(256) void scores_kernel() {
    __shared__ __align__(16) float Qs[16 * 128];
    __shared__ __align__(16) float Ks[16 * 128];

    const int bh = blockIdx.x;
    const int m0 = blockIdx.y * 128;
    const int n0 = blockIdx.z * 128;
    const int tid = threadIdx.x;
    const int tx = tid & 15, ty = tid >> 4;

    const __half* qb = g_q + (size_t)bh * Ss * Dd;
    const __half* kb = g_k + (size_t)bh * Ss * Dd;

    float acc[8][8];
#pragma unroll
    for (int i = 0; i < 8; i++)
#pragma unroll
        for (int j = 0; j < 8; j++) acc[i][j] = 0.f;

    const int lrow = tid >> 1;           // 0..127
    const int lkb  = (tid & 1) * 8;      // 0 or 8

    for (int kk = 0; kk < Dd; kk += 16) {
        const __half2* aptr = (const __half2*)(qb + (size_t)(m0 + lrow) * Dd + kk + lkb);
        const __half2* bptr = (const __half2*)(kb + (size_t)(n0 + lrow) * Dd + kk + lkb);
#pragma unroll
        for (int u = 0; u < 4; u++) {
            float2 av = __half22float2(aptr[u]);
            Qs[(lkb + 2 * u) * 128 + lrow]     = av.x;
            Qs[(lkb + 2 * u + 1) * 128 + lrow] = av.y;
            float2 bv = __half22float2(bptr[u]);
            Ks[(lkb + 2 * u) * 128 + lrow]     = bv.x;
            Ks[(lkb + 2 * u + 1) * 128 + lrow] = bv.y;
        }
        __syncthreads();
#pragma unroll
        for (int k = 0; k < 16; k++) {
            float4 a0 = *(const float4*)(Qs + k * 128 + ty * 8);
            float4 a1 = *(const float4*)(Qs + k * 128 + ty * 8 + 4);
            float4 b0 = *(const float4*)(Ks + k * 128 + tx * 8);
            float4 b1 = *(const float4*)(Ks + k * 128 + tx * 8 + 4);
            float a[8] = {a0.x, a0.y, a0.z, a0.w, a1.x, a1.y, a1.z, a1.w};
            float bb[8] = {b0.x, b0.y, b0.z, b0.w, b1.x, b1.y, b1.z, b1.w};
#pragma unroll
            for (int i = 0; i < 8; i++)
#pragma unroll
                for (int j = 0; j < 8; j++) acc[i][j] = fmaf(a[i], bb[j], acc[i][j]);
        }
        __syncthreads();
    }

#pragma unroll
    for (int i = 0; i < 8; i++)
#pragma unroll
        for (int j = 0; j < 8; j++)
            g_scores[((size_t)bh * Ss + m0 + ty * 8 + i) * Ss + n0 + tx * 8 + j] = acc[i][j];
}

// ==================================================================================
// Kernel 3: softmax per row, faithful fp16 rounding at each op boundary
//   grid: 1024  block: 256 (warp per row, 8 elems/lane)
// ==================================================================================
__global__ __launch_bounds__(256) void softmax_kernel() {
    const int row  = blockIdx.x * 8 + (threadIdx.x >> 5);  // 0..8191
    const int lane = threadIdx.x & 31;

    const float* srow = g_scores + (size_t)row * Ss;
    __half* arow = g_attn + (size_t)row * Ss;

    float l[8];
    float m = -1e30f;
#pragma unroll
    for (int i = 0; i < 8; i++) {
        // score rounded to fp16, then * fp16 scale (1/64 = exact exponent shift)
        float v = __half2float(__float2half(srow[lane + 32 * i])) * 0.015625f;
        l[i] = v;
        m = fmaxf(m, v);
    }
#pragma unroll
    for (int o = 16; o > 0; o >>= 1) m = fmaxf(m, __shfl_xor_sync(0xffffffffu, m, o));

    float e[8];
    float sum = 0.f;
#pragma unroll
    for (int i = 0; i < 8; i++) {
        float t = __half2float(__float2half(l[i] - m));       // fp16 subtract
        e[i] = __half2float(__float2half(__expf(0.f) * expf(t))); // fp16 exp (expf)
        sum += e[i];                                          // fp32 accumulate
    }
#pragma unroll
    for (int o = 16; o > 0; o >>= 1) sum += __shfl_xor_sync(0xffffffffu, sum, o);

#pragma unroll
    for (int i = 0; i < 8; i++)
        arow[lane + 32 * i] = __float2half(e[i] / sum);        // fp16 divide result
}

// ==================================================================================
// Kernel 4: SA = attn @ V  (per head: 256x4096, K=256), fp16 in, fp32 accum, fp16 out
//   grid: (BH, 2, 32)  block: 256, 128x128 tile, BK=16
// ==================================================================================
__global__ __launch_bounds__(256) void av_kernel() {
    __shared__ __align__(16) float As[16 * 128];  // As[t][m]
    __shared__ __align__(16) float Bs[16 * 128];  // Bs[t][n]

    const int bh = blockIdx.x;
    const int m0 = blockIdx.y * 128;   // s
    const int n0 = blockIdx.z * 128;   // d
    const int tid = threadIdx.x;
    const int tx = tid & 15, ty = tid >> 4;

    const __half* ab = g_attn + (size_t)bh * Ss * Ss;
    const __half* vb = g_v + (size_t)bh * Ss * Dd;

    float acc[8][8];
#pragma unroll
    for (int i = 0; i < 8; i++)
#pragma unroll
        for (int j = 0; j < 8; j++) acc[i][j] = 0.f;

    const int lrow = tid >> 1;          // A: 0..127 rows
    const int lkb  = (tid & 1) * 8;
    const int vrow = tid >> 4;          // B: 0..15 t-rows
    const int vcb  = (tid & 15) * 8;    // B: col base

    for (int kk = 0; kk < Ss; kk += 16) {
        const __half2* aptr = (const __half2*)(ab + (size_t)(m0 + lrow) * Ss + kk + lkb);
#pragma unroll
        for (int u = 0; u < 4; u++) {
            float2 av = __half22float2(aptr[u]);
            As[(lkb + 2 * u) * 128 + lrow]     = av.x;
            As[(lkb + 2 * u + 1) * 128 + lrow] = av.y;
        }
        const __half2* vptr = (const __half2*)(vb + (size_t)(kk + vrow) * Dd + n0 + vcb);
#pragma unroll
        for (int u = 0; u < 4; u++) {
            float2 bv = __half22float2(vptr[u]);
            Bs[vrow * 128 + vcb + 2 * u]     = bv.x;
            Bs[vrow * 128 + vcb + 2 * u + 1] = bv.y;
        }
        __syncthreads();
#pragma unroll
        for (int k = 0; k < 16; k++) {
            float4 a0 = *(const float4*)(As + k * 128 + ty * 8);
            float4 a1 = *(const float4*)(As + k * 128 + ty * 8 + 4);
            float4 b0 = *(const float4*)(Bs + k * 128 + tx * 8);
            float4 b1 = *(const float4*)(Bs + k * 128 + tx * 8 + 4);
            float a[8] = {a0.x, a0.y, a0.z, a0.w, a1.x, a1.y, a1.z, a1.w};
            float bb[8] = {b0.x, b0.y, b0.z, b0.w, b1.x, b1.y, b1.z, b1.w};
#pragma unroll
            for (int i = 0; i < 8; i++)
#pragma unroll
                for (int j = 0; j < 8; j++) acc[i][j] = fmaf(a[i], bb[j], acc[i][j]);
        }
        __syncthreads();
    }

#pragma unroll
    for (int i = 0; i < 8; i++)
#pragma unroll
        for (int j = 0; j < 8; j++)
            g_sa[((size_t)bh * Ss + m0 + ty * 8 + i) * Dd + n0 + tx * 8 + j] =
                __float2half(acc[i][j]);   // ref rounds SA to fp16 before fp32 cast
}

// ==================================================================================
// Kernel 5: recompose2d gather + output projection + bias
//   grid: (B*S, 8)  block: 256  dyn smem: 48 KB
// ==================================================================================
__global__ __launch_bounds__(256) void out_kernel(const float* __restrict__ w_out,
                                                  const float* __restrict__ b_out,
                                                  float* __restrict__ out) {
    extern __shared__ float sm5[];
    float* xs = sm5;            // [64][128]  channel x position (gathered SA)
    float* wT = sm5 + 8192;     // [64 c][64 o]

    const int bs = blockIdx.x;
    const int chunk = blockIdx.y;
    const int tid = threadIdx.x;
    const int b = bs >> 8, s = bs & 255;
    const int p0 = chunk * 128;

#pragma unroll
    for (int i = 0; i < 32; i++) {
        int idx = tid + i * 256;
        int c = idx >> 7, p = idx & 127;
        int pg = p0 + p;
        int h = pg >> 5, w = pg & 31;
        int sx = h >> 4, ii = h & 15;
        int sy = w >> 4, jj = w & 15;
        int head = (sx * 2 + sy) * 4 + (c >> 4);
        int d = (c & 15) * 256 + ii * 16 + jj;
        xs[idx] = __half2float(g_sa[((size_t)(b * NHh + head) * Ss + s) * Dd + d]);
    }
#pragma unroll
    for (int i = 0; i < 16; i++) {
        int idx = tid + i * 256;            // 0..4095
        int o = idx & 63, c = idx >> 6;
        wT[c * 64 + o] = w_out[o * 64 + c];
    }
    __syncthreads();

    const int tx = tid & 31, ty = tid >> 5;

    float acc[2][4][4];
#pragma unroll
    for (int r = 0; r < 2; r++)
#pragma unroll
        for (int i = 0; i < 4; i++)
#pragma unroll
            for (int j = 0; j < 4; j++) acc[r][i][j] = 0.f;

    for (int c = 0; c < 64; c++) {
        float xv[4];
#pragma unroll
        for (int i = 0; i < 4; i++) xv[i] = xs[c * 128 + tx + 32 * i];
        const float* wrow = wT + c * 64;
#pragma unroll
        for (int r = 0; r < 2; r++) {
            float4 w4 = *(const float4*)(wrow + r * 32 + ty * 4);
#pragma unroll
            for (int i = 0; i < 4; i++) {
                acc[r][i][0] = fmaf(xv[i], w4.x, acc[r][i][0]);
                acc[r][i][1] = fmaf(xv[i], w4.y, acc[r][i][1]);
                acc[r][i][2] = fmaf(xv[i], w4.z, acc[r][i][2]);
                acc[r][i][3] = fmaf(xv[i], w4.w, acc[r][i][3]);
            }
        }
    }

#pragma unroll
    for (int r = 0; r < 2; r++) {
#pragma unroll
        for (int j = 0; j < 4; j++) {
            int o = r * 32 + ty * 4 + j;
            float bias = b_out[o];
#pragma unroll
            for (int i = 0; i < 4; i++)
                out[((size_t)bs * 64 + o) * HWp + p0 + tx + 32 * i] = acc[r][i][j] + bias;
        }
    }
}

// ==================================================================================
extern "C" void kernel_launch(void* const* d_in, const int* in_sizes, int n_in,
                              void* d_out, int out_size) {
    const float* seq   = (const float*)d_in[0];
    const float* w_qkv = (const float*)d_in[1];
    const float* w_out = (const float*)d_in[2];
    const float* b_out = (const float*)d_in[3];
    float* out = (float*)d_out;

    cudaFuncSetAttribute(qkv_kernel, cudaFuncAttributeMaxDynamicSharedMemorySize,
                         (64 * 128 + 64 * 192) * 4);

    dim3 g1(Bb * Ss, 8);
    qkv_kernel<<<g1, 256, (64 * 128 + 64 * 192) * 4>>>(seq, w_qkv);

    dim3 g2(BHh, 2, 2);
    scores_kernel<<<g2, 256>>>();

    softmax_kernel<<<BHh * Ss / 8, 256>>>();

    dim3 g4(BHh, 2, 32);
    av_kernel<<<g4, 256>>>();

    dim3 g5(Bb * Ss, 8);
    out_kernel<<<g5, 256, (64 * 128 + 64 * 64) * 4>>>(w_out, b_out, out);
}

// round 2
// speedup vs baseline: 1.3623x; 1.3623x over previous
#include <cuda_runtime.h>
#include <cuda_fp16.h>
#include <cstdint>

// Problem constants (shapes are fixed by the dataset)
#define Bb   2
#define Ss   256
#define Ee   64
#define HWp  1024      // H*W = 32*32
#define CHh  4
#define NHh  16        // heads per batch = (XH*YH)*CH
#define BHh  32        // Bb*NHh
#define Dd   4096      // hd*hh*ww = 16*16*16

// -------------------- scratch (device globals; no allocation) --------------------
__device__ __half g_q[(size_t)BHh * Ss * Dd];      // 64 MB
__device__ __half g_k[(size_t)BHh * Ss * Dd];      // 64 MB
__device__ __half g_v[(size_t)BHh * Ss * Dd];      // 64 MB
__device__ float  g_scores[(size_t)BHh * Ss * Ss]; // 8 MB
__device__ __half g_attn[(size_t)BHh * Ss * Ss];   // 4 MB
__device__ __half g_sa[(size_t)BHh * Ss * Dd];     // 64 MB

// -------------------- mma helpers --------------------
__device__ __forceinline__ void mma_16816(float* c, const uint32_t* a, const uint32_t* b) {
    asm volatile(
        "mma.sync.aligned.m16n8k16.row.col.f32.f16.f16.f32 "
        "{%0,%1,%2,%3},{%4,%5,%6,%7},{%8,%9},{%0,%1,%2,%3};"
        : "+f"(c[0]), "+f"(c[1]), "+f"(c[2]), "+f"(c[3])
        : "r"(a[0]), "r"(a[1]), "r"(a[2]), "r"(a[3]), "r"(b[0]), "r"(b[1]));
}

__device__ __forceinline__ void ldsm_x4(uint32_t* r, const __half* p) {
    uint32_t addr = (uint32_t)__cvta_generic_to_shared(p);
    asm volatile("ldmatrix.sync.aligned.m8n8.x4.shared.b16 {%0,%1,%2,%3}, [%4];"
                 : "=r"(r[0]), "=r"(r[1]), "=r"(r[2]), "=r"(r[3]) : "r"(addr));
}
__device__ __forceinline__ void ldsm_x2(uint32_t* r, const __half* p) {
    uint32_t addr = (uint32_t)__cvta_generic_to_shared(p);
    asm volatile("ldmatrix.sync.aligned.m8n8.x2.shared.b16 {%0,%1}, [%2];"
                 : "=r"(r[0]), "=r"(r[1]) : "r"(addr));
}
__device__ __forceinline__ void ldsm_x2t(uint32_t* r, const __half* p) {
    uint32_t addr = (uint32_t)__cvta_generic_to_shared(p);
    asm volatile("ldmatrix.sync.aligned.m8n8.x2.trans.shared.b16 {%0,%1}, [%2];"
                 : "=r"(r[0]), "=r"(r[1]) : "r"(addr));
}

// ==================================================================================
// Kernel 1: QKV projection + decompose2d scatter into [b, head, s, d] fp16 layout
// ==================================================================================
__global__ __launch_bounds__(256) void qkv_kernel(const float* __restrict__ seq,
                                                  const float* __restrict__ w_qkv) {
    extern __shared__ float sm1[];
    float* xs = sm1;              // [64][128]
    float* wT = sm1 + 64 * 128;   // [64][192]

    const int bs    = blockIdx.x;
    const int chunk = blockIdx.y;
    const int tid   = threadIdx.x;
    const int p0    = chunk * 128;

    const float* src = seq + (size_t)bs * Ee * HWp + p0;
#pragma unroll
    for (int i = 0; i < 32; i++) {
        int idx = tid + i * 256;
        int e = idx >> 7, p = idx & 127;
        xs[idx] = src[(size_t)e * HWp + p];
    }
#pragma unroll
    for (int i = 0; i < 48; i++) {
        int idx = tid + i * 256;
        int o = idx % 192, e = idx / 192;
        wT[e * 192 + o] = w_qkv[o * 64 + e];
    }
    __syncthreads();

    const int tx = tid & 31;
    const int ty = tid >> 5;

    float acc[6][4][4];
#pragma unroll
    for (int r = 0; r < 6; r++)
#pragma unroll
        for (int i = 0; i < 4; i++)
#pragma unroll
            for (int j = 0; j < 4; j++) acc[r][i][j] = 0.f;

    for (int e = 0; e < 64; e++) {
        float xv[4];
#pragma unroll
        for (int i = 0; i < 4; i++) xv[i] = xs[e * 128 + tx + 32 * i];
        const float* wrow = wT + e * 192;
#pragma unroll
        for (int r = 0; r < 6; r++) {
            float4 w4 = *(const float4*)(wrow + r * 32 + ty * 4);
#pragma unroll
            for (int i = 0; i < 4; i++) {
                acc[r][i][0] = fmaf(xv[i], w4.x, acc[r][i][0]);
                acc[r][i][1] = fmaf(xv[i], w4.y, acc[r][i][1]);
                acc[r][i][2] = fmaf(xv[i], w4.z, acc[r][i][2]);
                acc[r][i][3] = fmaf(xv[i], w4.w, acc[r][i][3]);
            }
        }
    }

    const int b = bs >> 8, s = bs & 255;
#pragma unroll
    for (int r = 0; r < 6; r++) {
#pragma unroll
        for (int j = 0; j < 4; j++) {
            int o  = r * 32 + ty * 4 + j;
            int sp = o >> 6;
            int ch = (o >> 4) & 3;
            int dc = o & 15;
            __half* dst = (sp == 0) ? g_q : (sp == 1) ? g_k : g_v;
#pragma unroll
            for (int i = 0; i < 4; i++) {
                int p  = p0 + tx + 32 * i;
                int h  = p >> 5, w = p & 31;
                int sx = h >> 4, ii = h & 15;
                int sy = w >> 4, jj = w & 15;
                int head = (sx * 2 + sy) * 4 + ch;
                size_t di = ((size_t)(b * NHh + head) * Ss + s) * Dd
                          + dc * 256 + ii * 16 + jj;
                dst[di] = __float2half(acc[r][i][j]);
            }
        }
    }
}

// ==================================================================================
// Kernel 2: scores = Q @ K^T via HMMA (per head: 256x256, K=4096)
//   grid: (BH, 2, 2)  block: 256 (8 warps, 2m x 4n, warp tile 64x32)
//   fp16 in, fp32 accum, fp32 out
// ==================================================================================
__global__ __launch_bounds__(256) void scores_mma_kernel() {
    __shared__ __align__(16) __half Qs[128 * 64];
    __shared__ __align__(16) __half Ks[128 * 64];

    const int bh = blockIdx.x;
    const int m0 = blockIdx.y * 128;
    const int n0 = blockIdx.z * 128;
    const int tid = threadIdx.x, lane = tid & 31, warp = tid >> 5;
    const int wm = warp & 1;   // 0..1
    const int wn = warp >> 1;  // 0..3

    const __half* qb = g_q + (size_t)bh * Ss * Dd;
    const __half* kb = g_k + (size_t)bh * Ss * Dd;

    float acc[4][4][4];
#pragma unroll
    for (int mt = 0; mt < 4; mt++)
#pragma unroll
        for (int nt = 0; nt < 4; nt++)
#pragma unroll
            for (int c = 0; c < 4; c++) acc[mt][nt][c] = 0.f;

    for (int kk = 0; kk < Dd; kk += 64) {
        // load 128x64 Q and K tiles with XOR swizzle (8-half chunks)
#pragma unroll
        for (int i = 0; i < 4; i++) {
            int cid = tid + i * 256;          // 0..1023
            int row = cid >> 3, c8 = cid & 7;
            int sw = (c8 ^ (row & 7)) << 3;
            *(float4*)(Qs + row * 64 + sw) =
                *(const float4*)(qb + (size_t)(m0 + row) * Dd + kk + c8 * 8);
            *(float4*)(Ks + row * 64 + sw) =
                *(const float4*)(kb + (size_t)(n0 + row) * Dd + kk + c8 * 8);
        }
        __syncthreads();

#pragma unroll
        for (int ks = 0; ks < 4; ks++) {
            uint32_t a[4][4], b[4][2];
#pragma unroll
            for (int mt = 0; mt < 4; mt++) {
                int row = wm * 64 + mt * 16 + (lane & 15);
                int chk = ks * 2 + (lane >> 4);
                ldsm_x4(a[mt], Qs + row * 64 + ((chk ^ (row & 7)) << 3));
            }
#pragma unroll
            for (int nt = 0; nt < 4; nt++) {
                int row = wn * 32 + nt * 8 + (lane & 7);
                int chk = ks * 2 + ((lane >> 3) & 1);
                ldsm_x2(b[nt], Ks + row * 64 + ((chk ^ (row & 7)) << 3));
            }
#pragma unroll
            for (int mt = 0; mt < 4; mt++)
#pragma unroll
                for (int nt = 0; nt < 4; nt++)
                    mma_16816(acc[mt][nt], a[mt], b[nt]);
        }
        __syncthreads();
    }

    // epilogue: fp32 scores
#pragma unroll
    for (int mt = 0; mt < 4; mt++) {
#pragma unroll
        for (int nt = 0; nt < 4; nt++) {
            int r = m0 + wm * 64 + mt * 16 + (lane >> 2);
            int c = n0 + wn * 32 + nt * 8 + (lane & 3) * 2;
            float* dst = g_scores + ((size_t)bh * Ss + r) * Ss + c;
            dst[0] = acc[mt][nt][0];
            dst[1] = acc[mt][nt][1];
            dst[8 * Ss + 0] = acc[mt][nt][2];
            dst[8 * Ss + 1] = acc[mt][nt][3];
        }
    }
}

// ==================================================================================
// Kernel 3: softmax per row, faithful fp16 rounding at each op boundary
// ==================================================================================
__global__ __launch_bounds__(256) void softmax_kernel() {
    const int row  = blockIdx.x * 8 + (threadIdx.x >> 5);
    const int lane = threadIdx.x & 31;

    const float* srow = g_scores + (size_t)row * Ss;
    __half* arow = g_attn + (size_t)row * Ss;

    float l[8];
    float m = -1e30f;
#pragma unroll
    for (int i = 0; i < 8; i++) {
        float v = __half2float(__float2half(srow[lane + 32 * i])) * 0.015625f;
        l[i] = v;
        m = fmaxf(m, v);
    }
#pragma unroll
    for (int o = 16; o > 0; o >>= 1) m = fmaxf(m, __shfl_xor_sync(0xffffffffu, m, o));

    float e[8];
    float sum = 0.f;
#pragma unroll
    for (int i = 0; i < 8; i++) {
        float t = __half2float(__float2half(l[i] - m));
        e[i] = __half2float(__float2half(expf(t)));
        sum += e[i];
    }
#pragma unroll
    for (int o = 16; o > 0; o >>= 1) sum += __shfl_xor_sync(0xffffffffu, sum, o);

#pragma unroll
    for (int i = 0; i < 8; i++)
        arow[lane + 32 * i] = __float2half(e[i] / sum);
}

// ==================================================================================
// Kernel 4: SA = attn @ V via HMMA (per head: 256x4096, K=256)
//   grid: (BH, 2, 32)  block: 256 (8 warps, 2m x 4n, warp tile 64x32)
//   fp16 in, fp32 accum, fp16 out
// ==================================================================================
__global__ __launch_bounds__(256) void av_mma_kernel() {
    __shared__ __align__(16) __half As[128 * 64];   // attn tile [m][k]
    __shared__ __align__(16) __half Vs[64 * 128];   // V tile    [k][n]

    const int bh = blockIdx.x;
    const int m0 = blockIdx.y * 128;
    const int n0 = blockIdx.z * 128;
    const int tid = threadIdx.x, lane = tid & 31, warp = tid >> 5;
    const int wm = warp & 1;
    const int wn = warp >> 1;

    const __half* ab = g_attn + (size_t)bh * Ss * Ss;
    const __half* vb = g_v + (size_t)bh * Ss * Dd;

    float acc[4][4][4];
#pragma unroll
    for (int mt = 0; mt < 4; mt++)
#pragma unroll
        for (int nt = 0; nt < 4; nt++)
#pragma unroll
            for (int c = 0; c < 4; c++) acc[mt][nt][c] = 0.f;

    for (int kk = 0; kk < Ss; kk += 64) {
        // attn tile: 128 rows x 8 chunks
#pragma unroll
        for (int i = 0; i < 4; i++) {
            int cid = tid + i * 256;
            int row = cid >> 3, c8 = cid & 7;
            int sw = (c8 ^ (row & 7)) << 3;
            *(float4*)(As + row * 64 + sw) =
                *(const float4*)(ab + (size_t)(m0 + row) * Ss + kk + c8 * 8);
        }
        // V tile: 64 rows x 16 chunks
#pragma unroll
        for (int i = 0; i < 4; i++) {
            int cid = tid + i * 256;
            int row = cid >> 4, c = cid & 15;
            int sw = (c ^ (row & 7)) << 3;
            *(float4*)(Vs + row * 128 + sw) =
                *(const float4*)(vb + (size_t)(kk + row) * Dd + n0 + c * 8);
        }
        __syncthreads();

#pragma unroll
        for (int ks = 0; ks < 4; ks++) {
            uint32_t a[4][4], b[4][2];
#pragma unroll
            for (int mt = 0; mt < 4; mt++) {
                int row = wm * 64 + mt * 16 + (lane & 15);
                int chk = ks * 2 + (lane >> 4);
                ldsm_x4(a[mt], As + row * 64 + ((chk ^ (row & 7)) << 3));
            }
#pragma unroll
            for (int nt = 0; nt < 4; nt++) {
                int row = ks * 16 + (lane & 15);              // k rows
                int chk = wn * 4 + nt;                         // n chunk
                ldsm_x2t(b[nt], Vs + row * 128 + ((chk ^ (row & 7)) << 3));
            }
#pragma unroll
            for (int mt = 0; mt < 4; mt++)
#pragma unroll
                for (int nt = 0; nt < 4; nt++)
                    mma_16816(acc[mt][nt], a[mt], b[nt]);
        }
        __syncthreads();
    }

    // epilogue: fp16 SA (ref rounds SA to fp16 before fp32 cast)
#pragma unroll
    for (int mt = 0; mt < 4; mt++) {
#pragma unroll
        for (int nt = 0; nt < 4; nt++) {
            int r = m0 + wm * 64 + mt * 16 + (lane >> 2);
            int c = n0 + wn * 32 + nt * 8 + (lane & 3) * 2;
            __half* dst = g_sa + ((size_t)bh * Ss + r) * Dd + c;
            *(__half2*)dst = __floats2half2_rn(acc[mt][nt][0], acc[mt][nt][1]);
            *(__half2*)(dst + 8 * Dd) = __floats2half2_rn(acc[mt][nt][2], acc[mt][nt][3]);
        }
    }
}

// ==================================================================================
// Kernel 5: recompose2d gather + output projection + bias
// ==================================================================================
__global__ __launch_bounds__(256) void out_kernel(const float* __restrict__ w_out,
                                                  const float* __restrict__ b_out,
                                                  float* __restrict__ out) {
    extern __shared__ float sm5[];
    float* xs = sm5;            // [64][128]
    float* wT = sm5 + 8192;     // [64 c][64 o]

    const int bs = blockIdx.x;
    const int chunk = blockIdx.y;
    const int tid = threadIdx.x;
    const int b = bs >> 8, s = bs & 255;
    const int p0 = chunk * 128;

#pragma unroll
    for (int i = 0; i < 32; i++) {
        int idx = tid + i * 256;
        int c = idx >> 7, p = idx & 127;
        int pg = p0 + p;
        int h = pg >> 5, w = pg & 31;
        int sx = h >> 4, ii = h & 15;
        int sy = w >> 4, jj = w & 15;
        int head = (sx * 2 + sy) * 4 + (c >> 4);
        int d = (c & 15) * 256 + ii * 16 + jj;
        xs[idx] = __half2float(g_sa[((size_t)(b * NHh + head) * Ss + s) * Dd + d]);
    }
#pragma unroll
    for (int i = 0; i < 16; i++) {
        int idx = tid + i * 256;
        int o = idx & 63, c = idx >> 6;
        wT[c * 64 + o] = w_out[o * 64 + c];
    }
    __syncthreads();

    const int tx = tid & 31, ty = tid >> 5;

    float acc[2][4][4];
#pragma unroll
    for (int r = 0; r < 2; r++)
#pragma unroll
        for (int i = 0; i < 4; i++)
#pragma unroll
            for (int j = 0; j < 4; j++) acc[r][i][j] = 0.f;

    for (int c = 0; c < 64; c++) {
        float xv[4];
#pragma unroll
        for (int i = 0; i < 4; i++) xv[i] = xs[c * 128 + tx + 32 * i];
        const float* wrow = wT + c * 64;
#pragma unroll
        for (int r = 0; r < 2; r++) {
            float4 w4 = *(const float4*)(wrow + r * 32 + ty * 4);
#pragma unroll
            for (int i = 0; i < 4; i++) {
                acc[r][i][0] = fmaf(xv[i], w4.x, acc[r][i][0]);
                acc[r][i][1] = fmaf(xv[i], w4.y, acc[r][i][1]);
                acc[r][i][2] = fmaf(xv[i], w4.z, acc[r][i][2]);
                acc[r][i][3] = fmaf(xv[i], w4.w, acc[r][i][3]);
            }
        }
    }

#pragma unroll
    for (int r = 0; r < 2; r++) {
#pragma unroll
        for (int j = 0; j < 4; j++) {
            int o = r * 32 + ty * 4 + j;
            float bias = b_out[o];
#pragma unroll
            for (int i = 0; i < 4; i++)
                out[((size_t)bs * 64 + o) * HWp + p0 + tx + 32 * i] = acc[r][i][j] + bias;
        }
    }
}

// ==================================================================================
extern "C" void kernel_launch(void* const* d_in, const int* in_sizes, int n_in,
                              void* d_out, int out_size) {
    const float* seq   = (const float*)d_in[0];
    const float* w_qkv = (const float*)d_in[1];
    const float* w_out = (const float*)d_in[2];
    const float* b_out = (const float*)d_in[3];
    float* out = (float*)d_out;

    cudaFuncSetAttribute(qkv_kernel, cudaFuncAttributeMaxDynamicSharedMemorySize,
                         (64 * 128 + 64 * 192) * 4);

    dim3 g1(Bb * Ss, 8);
    qkv_kernel<<<g1, 256, (64 * 128 + 64 * 192) * 4>>>(seq, w_qkv);

    dim3 g2(BHh, 2, 2);
    scores_mma_kernel<<<g2, 256>>>();

    softmax_kernel<<<BHh * Ss / 8, 256>>>();

    dim3 g4(BHh, 2, 32);
    av_mma_kernel<<<g4, 256>>>();

    dim3 g5(Bb * Ss, 8);
    out_kernel<<<g5, 256, (64 * 128 + 64 * 64) * 4>>>(w_out, b_out, out);
}

// round 3
// speedup vs baseline: 3.9538x; 2.9022x over previous
#include <cuda_runtime.h>
#include <cuda_fp16.h>
#include <cstdint>

// Problem constants (shapes are fixed by the dataset)
#define Bb   2
#define Ss   256
#define Ee   64
#define HWp  1024      // H*W = 32*32
#define CHh  4
#define NHh  16        // heads per batch = (XH*YH)*CH
#define BHh  32        // Bb*NHh
#define Dd   4096      // hd*hh*ww = 16*16*16

// -------------------- scratch (device globals; no allocation) --------------------
__device__ __half g_q[(size_t)BHh * Ss * Dd];      // 64 MB
__device__ __half g_k[(size_t)BHh * Ss * Dd];      // 64 MB
__device__ __half g_v[(size_t)BHh * Ss * Dd];      // 64 MB
__device__ float  g_scores[(size_t)BHh * Ss * Ss]; // 8 MB
__device__ __half g_attn[(size_t)BHh * Ss * Ss];   // 4 MB
__device__ __half g_sa[(size_t)BHh * Ss * Dd];     // 64 MB

// -------------------- mma helpers --------------------
__device__ __forceinline__ void mma_16816(float* c, const uint32_t* a, const uint32_t* b) {
    asm volatile(
        "mma.sync.aligned.m16n8k16.row.col.f32.f16.f16.f32 "
        "{%0,%1,%2,%3},{%4,%5,%6,%7},{%8,%9},{%0,%1,%2,%3};"
        : "+f"(c[0]), "+f"(c[1]), "+f"(c[2]), "+f"(c[3])
        : "r"(a[0]), "r"(a[1]), "r"(a[2]), "r"(a[3]), "r"(b[0]), "r"(b[1]));
}

__device__ __forceinline__ void ldsm_x4(uint32_t* r, const __half* p) {
    uint32_t addr = (uint32_t)__cvta_generic_to_shared(p);
    asm volatile("ldmatrix.sync.aligned.m8n8.x4.shared.b16 {%0,%1,%2,%3}, [%4];"
                 : "=r"(r[0]), "=r"(r[1]), "=r"(r[2]), "=r"(r[3]) : "r"(addr));
}
__device__ __forceinline__ void ldsm_x4t(uint32_t* r, const __half* p) {
    uint32_t addr = (uint32_t)__cvta_generic_to_shared(p);
    asm volatile("ldmatrix.sync.aligned.m8n8.x4.trans.shared.b16 {%0,%1,%2,%3}, [%4];"
                 : "=r"(r[0]), "=r"(r[1]), "=r"(r[2]), "=r"(r[3]) : "r"(addr));
}
__device__ __forceinline__ void ldsm_x2(uint32_t* r, const __half* p) {
    uint32_t addr = (uint32_t)__cvta_generic_to_shared(p);
    asm volatile("ldmatrix.sync.aligned.m8n8.x2.shared.b16 {%0,%1}, [%2];"
                 : "=r"(r[0]), "=r"(r[1]) : "r"(addr));
}
__device__ __forceinline__ void ldsm_x2t(uint32_t* r, const __half* p) {
    uint32_t addr = (uint32_t)__cvta_generic_to_shared(p);
    asm volatile("ldmatrix.sync.aligned.m8n8.x2.trans.shared.b16 {%0,%1}, [%2];"
                 : "=r"(r[0]), "=r"(r[1]) : "r"(addr));
}

__device__ __forceinline__ void split_f32(float v, __half& hi, __half& lo) {
    hi = __float2half_rn(v);
    lo = __float2half_rn(v - __half2float(hi));
}

// A-fragment (m16k16, row-major A) from transposed smem storage S[k][m]:
//   krow = (lane&7) + ((lane>>4)<<3), mcol offset = ((lane>>3)&1)<<3, via ldmatrix.x4.trans
#define A_TRANS_KROW(lane)  (((lane) & 7) + (((lane) >> 4) << 3))
#define A_TRANS_MOFF(lane)  ((((lane) >> 3) & 1) << 3)

// ==================================================================================
// Kernel 1: QKV projection via HMMA with fp16 hi/lo split (3 passes, ~fp32 accurate)
//   C[p, o] = sum_e seq[e, p] * w_qkv[o, e];  M=128 positions, N=192, K=64
//   grid: (B*S, 8)  block: 256 (8 warps = 2m x 4n, warp tile 64x48)
//   epilogue: decompose2d scatter + fp16 rounding into g_q/g_k/g_v
// ==================================================================================
#define XST 136   // X smem row stride (halves): 128 + 8 pad
#define WST 72    // W smem row stride (halves): 64 + 8 pad

__global__ __launch_bounds__(256) void qkv_mma_kernel(const float* __restrict__ seq,
                                                      const float* __restrict__ w_qkv) {
    extern __shared__ __half smq[];
    __half* Xhi = smq;                 // [64 e][136] (cols = p)
    __half* Xlo = Xhi + 64 * XST;
    __half* Whi = Xlo + 64 * XST;      // [192 o][72] (cols = e)
    __half* Wlo = Whi + 192 * WST;

    const int bs  = blockIdx.x;
    const int p0  = blockIdx.y * 128;
    const int tid = threadIdx.x, lane = tid & 31, warp = tid >> 5;
    const int wm = warp >> 2;          // 0..1 -> m block of 64
    const int wn = warp & 3;           // 0..3 -> n block of 48

    // ---- load X = seq[bs][e][p0..p0+127], split into hi/lo, store [e][p] ----
    const float* src = seq + (size_t)bs * Ee * HWp + p0;
#pragma unroll
    for (int i = 0; i < 8; i++) {
        int cid = tid + i * 256;           // 0..2047 float4s
        int e = cid >> 5, p4 = (cid & 31) * 4;
        float4 v = *(const float4*)(src + (size_t)e * HWp + p4);
        __half h0, l0, h1, l1, h2, l2, h3, l3;
        split_f32(v.x, h0, l0); split_f32(v.y, h1, l1);
        split_f32(v.z, h2, l2); split_f32(v.w, h3, l3);
        __half* dh = Xhi + e * XST + p4;
        dh[0] = h0; dh[1] = h1; dh[2] = h2; dh[3] = h3;
        __half* dl = Xlo + e * XST + p4;
        dl[0] = l0; dl[1] = l1; dl[2] = l2; dl[3] = l3;
    }
    // ---- load W = w_qkv[o][e], split, store [o][e] ----
#pragma unroll
    for (int i = 0; i < 12; i++) {
        int cid = tid + i * 256;           // 0..3071 float4s
        int o = cid >> 4, e4 = (cid & 15) * 4;
        float4 v = *(const float4*)(w_qkv + o * 64 + e4);
        __half h0, l0, h1, l1, h2, l2, h3, l3;
        split_f32(v.x, h0, l0); split_f32(v.y, h1, l1);
        split_f32(v.z, h2, l2); split_f32(v.w, h3, l3);
        __half* dh = Whi + o * WST + e4;
        dh[0] = h0; dh[1] = h1; dh[2] = h2; dh[3] = h3;
        __half* dl = Wlo + o * WST + e4;
        dl[0] = l0; dl[1] = l1; dl[2] = l2; dl[3] = l3;
    }
    __syncthreads();

    float acc[4][6][4];
#pragma unroll
    for (int mt = 0; mt < 4; mt++)
#pragma unroll
        for (int nt = 0; nt < 6; nt++)
#pragma unroll
            for (int c = 0; c < 4; c++) acc[mt][nt][c] = 0.f;

    const int akrow = A_TRANS_KROW(lane);
    const int amoff = A_TRANS_MOFF(lane);
    const int bnrow = lane & 7;
    const int bkoff = ((lane >> 3) & 1) * 8;

#pragma unroll
    for (int pass = 0; pass < 3; pass++) {
        const __half* Xp = (pass == 2) ? Xlo : Xhi;
        const __half* Wp = (pass == 1) ? Wlo : Whi;
#pragma unroll
        for (int ks = 0; ks < 4; ks++) {
            uint32_t a[4][4], b[6][2];
#pragma unroll
            for (int mt = 0; mt < 4; mt++)
                ldsm_x4t(a[mt], Xp + (ks * 16 + akrow) * XST
                                   + wm * 64 + mt * 16 + amoff);
#pragma unroll
            for (int nt = 0; nt < 6; nt++)
                ldsm_x2(b[nt], Wp + (wn * 48 + nt * 8 + bnrow) * WST
                                  + ks * 16 + bkoff);
#pragma unroll
            for (int mt = 0; mt < 4; mt++)
#pragma unroll
                for (int nt = 0; nt < 6; nt++)
                    mma_16816(acc[mt][nt], a[mt], b[nt]);
        }
    }

    // ---- epilogue: decompose2d scatter, fp16 rounding ----
    const int b = bs >> 8, s = bs & 255;
#pragma unroll
    for (int mt = 0; mt < 4; mt++) {
        int r0 = wm * 64 + mt * 16 + (lane >> 2);
#pragma unroll
        for (int nt = 0; nt < 6; nt++) {
            int ob = wn * 48 + nt * 8 + (lane & 3) * 2;
#pragma unroll
            for (int c = 0; c < 4; c++) {
                int o  = ob + (c & 1);
                int rr = r0 + (c >> 1) * 8;
                int p  = p0 + rr;
                int h  = p >> 5, w = p & 31;
                int hs = (h >> 4) * 2 + (w >> 4);
                int dspat = (h & 15) * 16 + (w & 15);
                int sp = o >> 6;
                int ch = (o >> 4) & 3;
                int dc = o & 15;
                __half* dst = (sp == 0) ? g_q : (sp == 1) ? g_k : g_v;
                size_t di = ((size_t)(b * NHh + hs * 4 + ch) * Ss + s) * Dd
                          + dc * 256 + dspat;
                dst[di] = __float2half(acc[mt][nt][c]);
            }
        }
    }
}

// ==================================================================================
// Kernel 2: scores = Q @ K^T via HMMA, 64x64 tiles for occupancy
//   grid: (BH, 4, 4)  block: 128 (4 warps, 2m x 2n, warp tile 32x32)
// ==================================================================================
__global__ __launch_bounds__(128) void scores_mma_kernel() {
    __shared__ __align__(16) __half Qs[64 * 64];
    __shared__ __align__(16) __half Ks[64 * 64];

    const int bh = blockIdx.x;
    const int m0 = blockIdx.y * 64;
    const int n0 = blockIdx.z * 64;
    const int tid = threadIdx.x, lane = tid & 31, warp = tid >> 5;
    const int wm = warp >> 1;   // 0..1
    const int wn = warp & 1;    // 0..1

    const __half* qb = g_q + (size_t)bh * Ss * Dd;
    const __half* kb = g_k + (size_t)bh * Ss * Dd;

    float acc[2][4][4];
#pragma unroll
    for (int mt = 0; mt < 2; mt++)
#pragma unroll
        for (int nt = 0; nt < 4; nt++)
#pragma unroll
            for (int c = 0; c < 4; c++) acc[mt][nt][c] = 0.f;

    for (int kk = 0; kk < Dd; kk += 64) {
        // load 64x64 Q and K tiles with XOR swizzle (8-half chunks)
#pragma unroll
        for (int i = 0; i < 4; i++) {
            int cid = tid + i * 128;          // 0..511
            int row = cid >> 3, c8 = cid & 7;
            int sw = (c8 ^ (row & 7)) << 3;
            *(float4*)(Qs + row * 64 + sw) =
                *(const float4*)(qb + (size_t)(m0 + row) * Dd + kk + c8 * 8);
            *(float4*)(Ks + row * 64 + sw) =
                *(const float4*)(kb + (size_t)(n0 + row) * Dd + kk + c8 * 8);
        }
        __syncthreads();

#pragma unroll
        for (int ks = 0; ks < 4; ks++) {
            uint32_t a[2][4], b[4][2];
#pragma unroll
            for (int mt = 0; mt < 2; mt++) {
                int row = wm * 32 + mt * 16 + (lane & 15);
                int chk = ks * 2 + (lane >> 4);
                ldsm_x4(a[mt], Qs + row * 64 + ((chk ^ (row & 7)) << 3));
            }
#pragma unroll
            for (int nt = 0; nt < 4; nt++) {
                int row = wn * 32 + nt * 8 + (lane & 7);
                int chk = ks * 2 + ((lane >> 3) & 1);
                ldsm_x2(b[nt], Ks + row * 64 + ((chk ^ (row & 7)) << 3));
            }
#pragma unroll
            for (int mt = 0; mt < 2; mt++)
#pragma unroll
                for (int nt = 0; nt < 4; nt++)
                    mma_16816(acc[mt][nt], a[mt], b[nt]);
        }
        __syncthreads();
    }

#pragma unroll
    for (int mt = 0; mt < 2; mt++) {
#pragma unroll
        for (int nt = 0; nt < 4; nt++) {
            int r = m0 + wm * 32 + mt * 16 + (lane >> 2);
            int c = n0 + wn * 32 + nt * 8 + (lane & 3) * 2;
            float* dst = g_scores + ((size_t)bh * Ss + r) * Ss + c;
            dst[0] = acc[mt][nt][0];
            dst[1] = acc[mt][nt][1];
            dst[8 * Ss + 0] = acc[mt][nt][2];
            dst[8 * Ss + 1] = acc[mt][nt][3];
        }
    }
}

// ==================================================================================
// Kernel 3: softmax per row, faithful fp16 rounding at each op boundary
// ==================================================================================
__global__ __launch_bounds__(256) void softmax_kernel() {
    const int row  = blockIdx.x * 8 + (threadIdx.x >> 5);
    const int lane = threadIdx.x & 31;

    const float* srow = g_scores + (size_t)row * Ss;
    __half* arow = g_attn + (size_t)row * Ss;

    float l[8];
    float m = -1e30f;
#pragma unroll
    for (int i = 0; i < 8; i++) {
        float v = __half2float(__float2half(srow[lane + 32 * i])) * 0.015625f;
        l[i] = v;
        m = fmaxf(m, v);
    }
#pragma unroll
    for (int o = 16; o > 0; o >>= 1) m = fmaxf(m, __shfl_xor_sync(0xffffffffu, m, o));

    float e[8];
    float sum = 0.f;
#pragma unroll
    for (int i = 0; i < 8; i++) {
        float t = __half2float(__float2half(l[i] - m));
        e[i] = __half2float(__float2half(expf(t)));
        sum += e[i];
    }
#pragma unroll
    for (int o = 16; o > 0; o >>= 1) sum += __shfl_xor_sync(0xffffffffu, sum, o);

#pragma unroll
    for (int i = 0; i < 8; i++)
        arow[lane + 32 * i] = __float2half(e[i] / sum);
}

// ==================================================================================
// Kernel 4: SA = attn @ V via HMMA (per head: 256x4096, K=256)
//   grid: (BH, 2, 32)  block: 256 (8 warps, 2m x 4n, warp tile 64x32)
// ==================================================================================
__global__ __launch_bounds__(256) void av_mma_kernel() {
    __shared__ __align__(16) __half As[128 * 64];   // attn tile [m][k]
    __shared__ __align__(16) __half Vs[64 * 128];   // V tile    [k][n]

    const int bh = blockIdx.x;
    const int m0 = blockIdx.y * 128;
    const int n0 = blockIdx.z * 128;
    const int tid = threadIdx.x, lane = tid & 31, warp = tid >> 5;
    const int wm = warp & 1;
    const int wn = warp >> 1;

    const __half* ab = g_attn + (size_t)bh * Ss * Ss;
    const __half* vb = g_v + (size_t)bh * Ss * Dd;

    float acc[4][4][4];
#pragma unroll
    for (int mt = 0; mt < 4; mt++)
#pragma unroll
        for (int nt = 0; nt < 4; nt++)
#pragma unroll
            for (int c = 0; c < 4; c++) acc[mt][nt][c] = 0.f;

    for (int kk = 0; kk < Ss; kk += 64) {
#pragma unroll
        for (int i = 0; i < 4; i++) {
            int cid = tid + i * 256;
            int row = cid >> 3, c8 = cid & 7;
            int sw = (c8 ^ (row & 7)) << 3;
            *(float4*)(As + row * 64 + sw) =
                *(const float4*)(ab + (size_t)(m0 + row) * Ss + kk + c8 * 8);
        }
#pragma unroll
        for (int i = 0; i < 4; i++) {
            int cid = tid + i * 256;
            int row = cid >> 4, c = cid & 15;
            int sw = (c ^ (row & 7)) << 3;
            *(float4*)(Vs + row * 128 + sw) =
                *(const float4*)(vb + (size_t)(kk + row) * Dd + n0 + c * 8);
        }
        __syncthreads();

#pragma unroll
        for (int ks = 0; ks < 4; ks++) {
            uint32_t a[4][4], b[4][2];
#pragma unroll
            for (int mt = 0; mt < 4; mt++) {
                int row = wm * 64 + mt * 16 + (lane & 15);
                int chk = ks * 2 + (lane >> 4);
                ldsm_x4(a[mt], As + row * 64 + ((chk ^ (row & 7)) << 3));
            }
#pragma unroll
            for (int nt = 0; nt < 4; nt++) {
                int row = ks * 16 + (lane & 15);
                int chk = wn * 4 + nt;
                ldsm_x2t(b[nt], Vs + row * 128 + ((chk ^ (row & 7)) << 3));
            }
#pragma unroll
            for (int mt = 0; mt < 4; mt++)
#pragma unroll
                for (int nt = 0; nt < 4; nt++)
                    mma_16816(acc[mt][nt], a[mt], b[nt]);
        }
        __syncthreads();
    }

#pragma unroll
    for (int mt = 0; mt < 4; mt++) {
#pragma unroll
        for (int nt = 0; nt < 4; nt++) {
            int r = m0 + wm * 64 + mt * 16 + (lane >> 2);
            int c = n0 + wn * 32 + nt * 8 + (lane & 3) * 2;
            __half* dst = g_sa + ((size_t)bh * Ss + r) * Dd + c;
            *(__half2*)dst = __floats2half2_rn(acc[mt][nt][0], acc[mt][nt][1]);
            *(__half2*)(dst + 8 * Dd) = __floats2half2_rn(acc[mt][nt][2], acc[mt][nt][3]);
        }
    }
}

// ==================================================================================
// Kernel 5: recompose2d gather + output projection via HMMA (2-pass w hi/lo)
//   C[p, o] = sum_c sa[c, p] * w_out[o, c] + b_out[o];  M=128, N=64, K=64
//   grid: (B*S, 8)  block: 256 (8 warps = 4m x 2n, warp tile 32x32)
// ==================================================================================
__global__ __launch_bounds__(256) void out_mma_kernel(const float* __restrict__ w_out,
                                                      const float* __restrict__ b_out,
                                                      float* __restrict__ out) {
    __shared__ __align__(16) __half Ah[64 * XST];    // gathered SA [c][p] (exact fp16)
    __shared__ __align__(16) __half Whi2[64 * WST];  // [o][c]
    __shared__ __align__(16) __half Wlo2[64 * WST];

    const int bs  = blockIdx.x;
    const int p0  = blockIdx.y * 128;
    const int tid = threadIdx.x, lane = tid & 31, warp = tid >> 5;
    const int wm = warp >> 1;          // 0..3 -> m block of 32
    const int wn = warp & 1;           // 0..1 -> n block of 32
    const int b = bs >> 8, s = bs & 255;

    // gather SA (recompose2d) into [c][p]
#pragma unroll
    for (int i = 0; i < 32; i++) {
        int idx = tid + i * 256;           // 0..8191
        int c = idx >> 7, p = idx & 127;
        int pg = p0 + p;
        int h = pg >> 5, w = pg & 31;
        int head = ((h >> 4) * 2 + (w >> 4)) * 4 + (c >> 4);
        int d = (c & 15) * 256 + (h & 15) * 16 + (w & 15);
        Ah[c * XST + p] = g_sa[((size_t)(b * NHh + head) * Ss + s) * Dd + d];
    }
    // W split hi/lo
#pragma unroll
    for (int i = 0; i < 4; i++) {
        int cid = tid + i * 256;           // 0..1023 float4s
        int o = cid >> 4, e4 = (cid & 15) * 4;
        float4 v = *(const float4*)(w_out + o * 64 + e4);
        __half h0, l0, h1, l1, h2, l2, h3, l3;
        split_f32(v.x, h0, l0); split_f32(v.y, h1, l1);
        split_f32(v.z, h2, l2); split_f32(v.w, h3, l3);
        __half* dh = Whi2 + o * WST + e4;
        dh[0] = h0; dh[1] = h1; dh[2] = h2; dh[3] = h3;
        __half* dl = Wlo2 + o * WST + e4;
        dl[0] = l0; dl[1] = l1; dl[2] = l2; dl[3] = l3;
    }
    __syncthreads();

    float acc[2][4][4];
#pragma unroll
    for (int mt = 0; mt < 2; mt++)
#pragma unroll
        for (int nt = 0; nt < 4; nt++)
#pragma unroll
            for (int c = 0; c < 4; c++) acc[mt][nt][c] = 0.f;

    const int akrow = A_TRANS_KROW(lane);
    const int amoff = A_TRANS_MOFF(lane);
    const int bnrow = lane & 7;
    const int bkoff = ((lane >> 3) & 1) * 8;

#pragma unroll
    for (int pass = 0; pass < 2; pass++) {
        const __half* Wp = pass ? Wlo2 : Whi2;
#pragma unroll
        for (int ks = 0; ks < 4; ks++) {
            uint32_t a[2][4], bfr[4][2];
#pragma unroll
            for (int mt = 0; mt < 2; mt++)
                ldsm_x4t(a[mt], Ah + (ks * 16 + akrow) * XST
                                   + wm * 32 + mt * 16 + amoff);
#pragma unroll
            for (int nt = 0; nt < 4; nt++)
                ldsm_x2(bfr[nt], Wp + (wn * 32 + nt * 8 + bnrow) * WST
                                    + ks * 16 + bkoff);
#pragma unroll
            for (int mt = 0; mt < 2; mt++)
#pragma unroll
                for (int nt = 0; nt < 4; nt++)
                    mma_16816(acc[mt][nt], a[mt], bfr[nt]);
        }
    }

    // epilogue: out[bs][o][p] = acc + bias
#pragma unroll
    for (int mt = 0; mt < 2; mt++) {
        int r0 = wm * 32 + mt * 16 + (lane >> 2);
#pragma unroll
        for (int nt = 0; nt < 4; nt++) {
            int ob = wn * 32 + nt * 8 + (lane & 3) * 2;
#pragma unroll
            for (int c = 0; c < 4; c++) {
                int o  = ob + (c & 1);
                int rr = r0 + (c >> 1) * 8;
                out[((size_t)bs * 64 + o) * HWp + p0 + rr] = acc[mt][nt][c] + b_out[o];
            }
        }
    }
}

// ==================================================================================
extern "C" void kernel_launch(void* const* d_in, const int* in_sizes, int n_in,
                              void* d_out, int out_size) {
    const float* seq   = (const float*)d_in[0];
    const float* w_qkv = (const float*)d_in[1];
    const float* w_out = (const float*)d_in[2];
    const float* b_out = (const float*)d_in[3];
    float* out = (float*)d_out;

    const int qkv_smem = (2 * 64 * XST + 2 * 192 * WST) * (int)sizeof(__half);
    cudaFuncSetAttribute(qkv_mma_kernel, cudaFuncAttributeMaxDynamicSharedMemorySize,
                         qkv_smem);

    dim3 g1(Bb * Ss, 8);
    qkv_mma_kernel<<<g1, 256, qkv_smem>>>(seq, w_qkv);

    dim3 g2(BHh, 4, 4);
    scores_mma_kernel<<<g2, 128>>>();

    softmax_kernel<<<BHh * Ss / 8, 256>>>();

    dim3 g4(BHh, 2, 32);
    av_mma_kernel<<<g4, 256>>>();

    dim3 g5(Bb * Ss, 8);
    out_mma_kernel<<<g5, 256>>>(w_out, b_out, out);
}

// round 4
// speedup vs baseline: 4.5165x; 1.1423x over previous
#include <cuda_runtime.h>
#include <cuda_fp16.h>
#include <cstdint>

// Problem constants (shapes are fixed by the dataset)
#define Bb   2
#define Ss   256
#define Ee   64
#define HWp  1024      // H*W = 32*32
#define CHh  4
#define NHh  16        // heads per batch = (XH*YH)*CH
#define BHh  32        // Bb*NHh
#define Dd   4096      // hd*hh*ww = 16*16*16

// -------------------- scratch (device globals; no allocation) --------------------
__device__ __half g_q[(size_t)BHh * Ss * Dd];      // 64 MB
__device__ __half g_k[(size_t)BHh * Ss * Dd];      // 64 MB
__device__ __half g_v[(size_t)BHh * Ss * Dd];      // 64 MB
__device__ float  g_scores[(size_t)BHh * Ss * Ss]; // 8 MB
__device__ __half g_attn[(size_t)BHh * Ss * Ss];   // 4 MB
__device__ __half g_sa[(size_t)BHh * Ss * Dd];     // 64 MB

// -------------------- mma / ldmatrix / cp.async helpers --------------------
__device__ __forceinline__ void mma_16816(float* c, const uint32_t* a, const uint32_t* b) {
    asm volatile(
        "mma.sync.aligned.m16n8k16.row.col.f32.f16.f16.f32 "
        "{%0,%1,%2,%3},{%4,%5,%6,%7},{%8,%9},{%0,%1,%2,%3};"
        : "+f"(c[0]), "+f"(c[1]), "+f"(c[2]), "+f"(c[3])
        : "r"(a[0]), "r"(a[1]), "r"(a[2]), "r"(a[3]), "r"(b[0]), "r"(b[1]));
}

__device__ __forceinline__ void ldsm_x4(uint32_t* r, const __half* p) {
    uint32_t addr = (uint32_t)__cvta_generic_to_shared(p);
    asm volatile("ldmatrix.sync.aligned.m8n8.x4.shared.b16 {%0,%1,%2,%3}, [%4];"
                 : "=r"(r[0]), "=r"(r[1]), "=r"(r[2]), "=r"(r[3]) : "r"(addr));
}
__device__ __forceinline__ void ldsm_x4t(uint32_t* r, const __half* p) {
    uint32_t addr = (uint32_t)__cvta_generic_to_shared(p);
    asm volatile("ldmatrix.sync.aligned.m8n8.x4.trans.shared.b16 {%0,%1,%2,%3}, [%4];"
                 : "=r"(r[0]), "=r"(r[1]), "=r"(r[2]), "=r"(r[3]) : "r"(addr));
}
__device__ __forceinline__ void ldsm_x2(uint32_t* r, const __half* p) {
    uint32_t addr = (uint32_t)__cvta_generic_to_shared(p);
    asm volatile("ldmatrix.sync.aligned.m8n8.x2.shared.b16 {%0,%1}, [%2];"
                 : "=r"(r[0]), "=r"(r[1]) : "r"(addr));
}
__device__ __forceinline__ void ldsm_x2t(uint32_t* r, const __half* p) {
    uint32_t addr = (uint32_t)__cvta_generic_to_shared(p);
    asm volatile("ldmatrix.sync.aligned.m8n8.x2.trans.shared.b16 {%0,%1}, [%2];"
                 : "=r"(r[0]), "=r"(r[1]) : "r"(addr));
}

__device__ __forceinline__ void cp16(__half* smem, const __half* gmem) {
    uint32_t s = (uint32_t)__cvta_generic_to_shared(smem);
    asm volatile("cp.async.cg.shared.global [%0], [%1], 16;" :: "r"(s), "l"(gmem));
}
__device__ __forceinline__ void cp_commit() {
    asm volatile("cp.async.commit_group;");
}
template <int N>
__device__ __forceinline__ void cp_wait() {
    asm volatile("cp.async.wait_group %0;" :: "n"(N));
}

__device__ __forceinline__ void split_f32(float v, __half& hi, __half& lo) {
    hi = __float2half_rn(v);
    lo = __float2half_rn(v - __half2float(hi));
}

// A-fragment (m16k16, row-major A) from transposed smem storage S[k][m]
#define A_TRANS_KROW(lane)  (((lane) & 7) + (((lane) >> 4) << 3))
#define A_TRANS_MOFF(lane)  ((((lane) >> 3) & 1) << 3)

// ==================================================================================
// Kernel 1: QKV projection via HMMA with fp16 hi/lo split (3 passes)
//   C[p, o] = sum_e seq[e, p] * w_qkv[o, e];  M=128 positions, N=192, K=64
//   grid: (B*S, 8)  block: 256 (8 warps = 2m x 4n, warp tile 64x48)
//   epilogue: stage to smem, coalesced 16B scatter (decompose2d)
// ==================================================================================
#define XST 136   // X smem row stride (halves): 128 + 8 pad
#define WST 72    // W smem row stride (halves): 64 + 8 pad
#define OST 136   // out staging stride

__global__ __launch_bounds__(256) void qkv_mma_kernel(const float* __restrict__ seq,
                                                      const float* __restrict__ w_qkv) {
    extern __shared__ __half smq[];
    __half* Xhi = smq;                 // [64 e][136] (cols = p)
    __half* Xlo = Xhi + 64 * XST;
    __half* Whi = Xlo + 64 * XST;      // [192 o][72] (cols = e)
    __half* Wlo = Whi + 192 * WST;

    const int bs  = blockIdx.x;
    const int p0  = blockIdx.y * 128;
    const int tid = threadIdx.x, lane = tid & 31, warp = tid >> 5;
    const int wm = warp >> 2;          // 0..1 -> m block of 64
    const int wn = warp & 3;           // 0..3 -> n block of 48

    // ---- load X = seq[bs][e][p0..p0+127], split into hi/lo, store [e][p] ----
    const float* src = seq + (size_t)bs * Ee * HWp + p0;
#pragma unroll
    for (int i = 0; i < 8; i++) {
        int cid = tid + i * 256;           // 0..2047 float4s
        int e = cid >> 5, p4 = (cid & 31) * 4;
        float4 v = *(const float4*)(src + (size_t)e * HWp + p4);
        __half h0, l0, h1, l1, h2, l2, h3, l3;
        split_f32(v.x, h0, l0); split_f32(v.y, h1, l1);
        split_f32(v.z, h2, l2); split_f32(v.w, h3, l3);
        __half* dh = Xhi + e * XST + p4;
        dh[0] = h0; dh[1] = h1; dh[2] = h2; dh[3] = h3;
        __half* dl = Xlo + e * XST + p4;
        dl[0] = l0; dl[1] = l1; dl[2] = l2; dl[3] = l3;
    }
    // ---- load W = w_qkv[o][e], split, store [o][e] ----
#pragma unroll
    for (int i = 0; i < 12; i++) {
        int cid = tid + i * 256;           // 0..3071 float4s
        int o = cid >> 4, e4 = (cid & 15) * 4;
        float4 v = *(const float4*)(w_qkv + o * 64 + e4);
        __half h0, l0, h1, l1, h2, l2, h3, l3;
        split_f32(v.x, h0, l0); split_f32(v.y, h1, l1);
        split_f32(v.z, h2, l2); split_f32(v.w, h3, l3);
        __half* dh = Whi + o * WST + e4;
        dh[0] = h0; dh[1] = h1; dh[2] = h2; dh[3] = h3;
        __half* dl = Wlo + o * WST + e4;
        dl[0] = l0; dl[1] = l1; dl[2] = l2; dl[3] = l3;
    }
    __syncthreads();

    float acc[4][6][4];
#pragma unroll
    for (int mt = 0; mt < 4; mt++)
#pragma unroll
        for (int nt = 0; nt < 6; nt++)
#pragma unroll
            for (int c = 0; c < 4; c++) acc[mt][nt][c] = 0.f;

    const int akrow = A_TRANS_KROW(lane);
    const int amoff = A_TRANS_MOFF(lane);
    const int bnrow = lane & 7;
    const int bkoff = ((lane >> 3) & 1) * 8;

#pragma unroll
    for (int pass = 0; pass < 3; pass++) {
        const __half* Xp = (pass == 2) ? Xlo : Xhi;
        const __half* Wp = (pass == 1) ? Wlo : Whi;
#pragma unroll
        for (int ks = 0; ks < 4; ks++) {
            uint32_t a[4][4], b[6][2];
#pragma unroll
            for (int mt = 0; mt < 4; mt++)
                ldsm_x4t(a[mt], Xp + (ks * 16 + akrow) * XST
                                   + wm * 64 + mt * 16 + amoff);
#pragma unroll
            for (int nt = 0; nt < 6; nt++)
                ldsm_x2(b[nt], Wp + (wn * 48 + nt * 8 + bnrow) * WST
                                  + ks * 16 + bkoff);
#pragma unroll
            for (int mt = 0; mt < 4; mt++)
#pragma unroll
                for (int nt = 0; nt < 6; nt++)
                    mma_16816(acc[mt][nt], a[mt], b[nt]);
        }
    }

    // ---- epilogue: stage fp16 results to smem Out[o][p_local] ----
    __syncthreads();                       // all MMA smem reads done; reuse region
    __half* OutS = smq;                    // [192][OST]
#pragma unroll
    for (int mt = 0; mt < 4; mt++) {
        int r0 = wm * 64 + mt * 16 + (lane >> 2);
#pragma unroll
        for (int nt = 0; nt < 6; nt++) {
            int ob = wn * 48 + nt * 8 + (lane & 3) * 2;
#pragma unroll
            for (int c = 0; c < 4; c++) {
                int o  = ob + (c & 1);
                int pl = r0 + (c >> 1) * 8;
                OutS[o * OST + pl] = __float2half(acc[mt][nt][c]);
            }
        }
    }
    __syncthreads();

    // ---- coalesced scatter: 192 o x 4 h x 2 sy segments of 16 halves (32B) ----
    const int b = bs >> 8, s = bs & 255;
    const int h_base = blockIdx.y * 4;     // p = 32*h_local + w
#pragma unroll
    for (int it = 0; it < 6; it++) {
        int seg = tid + it * 256;          // 0..1535
        int o   = seg >> 3;
        int sub = seg & 7;
        int hl  = sub >> 1;                // local h row 0..3
        int sy  = sub & 1;
        int h   = h_base + hl;
        int sx = h >> 4, ii = h & 15;
        int sp = o >> 6, ch = (o >> 4) & 3, dc = o & 15;
        int head = (sx * 2 + sy) * 4 + ch;
        __half* dst = (sp == 0) ? g_q : (sp == 1) ? g_k : g_v;
        size_t di = ((size_t)(b * NHh + head) * Ss + s) * Dd + dc * 256 + ii * 16;
        const uint4* sp4 = (const uint4*)(OutS + o * OST + hl * 32 + sy * 16);
        *(uint4*)(dst + di)     = sp4[0];
        *(uint4*)(dst + di + 8) = sp4[1];
    }
}

// ==================================================================================
// Kernel 2: scores = Q @ K^T via HMMA, 64x64 tiles, cp.async 2-stage pipeline
//   grid: (BH, 4, 4)  block: 128 (4 warps, 2m x 2n, warp tile 32x32)
// ==================================================================================
__global__ __launch_bounds__(128) void scores_mma_kernel() {
    __shared__ __align__(16) __half Qs[2][64 * 64];
    __shared__ __align__(16) __half Ks[2][64 * 64];

    const int bh = blockIdx.x;
    const int m0 = blockIdx.y * 64;
    const int n0 = blockIdx.z * 64;
    const int tid = threadIdx.x, lane = tid & 31, warp = tid >> 5;
    const int wm = warp >> 1;   // 0..1
    const int wn = warp & 1;    // 0..1

    const __half* qb = g_q + (size_t)bh * Ss * Dd;
    const __half* kb = g_k + (size_t)bh * Ss * Dd;

    float acc[2][4][4];
#pragma unroll
    for (int mt = 0; mt < 2; mt++)
#pragma unroll
        for (int nt = 0; nt < 4; nt++)
#pragma unroll
            for (int c = 0; c < 4; c++) acc[mt][nt][c] = 0.f;

    // per-thread load coords (4 float4s per tensor per stage)
    auto issue_loads = [&](int buf, int kk) {
#pragma unroll
        for (int i = 0; i < 4; i++) {
            int cid = tid + i * 128;          // 0..511
            int row = cid >> 3, c8 = cid & 7;
            int sw = (c8 ^ (row & 7)) << 3;
            cp16(Qs[buf] + row * 64 + sw, qb + (size_t)(m0 + row) * Dd + kk + c8 * 8);
            cp16(Ks[buf] + row * 64 + sw, kb + (size_t)(n0 + row) * Dd + kk + c8 * 8);
        }
        cp_commit();
    };

    issue_loads(0, 0);
    const int T = Dd / 64;   // 64
    for (int t = 0; t < T; t++) {
        if (t + 1 < T) {
            issue_loads((t + 1) & 1, (t + 1) * 64);
            cp_wait<1>();
        } else {
            cp_wait<0>();
        }
        __syncthreads();

        const __half* Qb = Qs[t & 1];
        const __half* Kb = Ks[t & 1];
#pragma unroll
        for (int ks = 0; ks < 4; ks++) {
            uint32_t a[2][4], b[4][2];
#pragma unroll
            for (int mt = 0; mt < 2; mt++) {
                int row = wm * 32 + mt * 16 + (lane & 15);
                int chk = ks * 2 + (lane >> 4);
                ldsm_x4(a[mt], Qb + row * 64 + ((chk ^ (row & 7)) << 3));
            }
#pragma unroll
            for (int nt = 0; nt < 4; nt++) {
                int row = wn * 32 + nt * 8 + (lane & 7);
                int chk = ks * 2 + ((lane >> 3) & 1);
                ldsm_x2(b[nt], Kb + row * 64 + ((chk ^ (row & 7)) << 3));
            }
#pragma unroll
            for (int mt = 0; mt < 2; mt++)
#pragma unroll
                for (int nt = 0; nt < 4; nt++)
                    mma_16816(acc[mt][nt], a[mt], b[nt]);
        }
        __syncthreads();   // protect buf (t&1) before it is re-filled at t+1
    }

#pragma unroll
    for (int mt = 0; mt < 2; mt++) {
#pragma unroll
        for (int nt = 0; nt < 4; nt++) {
            int r = m0 + wm * 32 + mt * 16 + (lane >> 2);
            int c = n0 + wn * 32 + nt * 8 + (lane & 3) * 2;
            float* dst = g_scores + ((size_t)bh * Ss + r) * Ss + c;
            dst[0] = acc[mt][nt][0];
            dst[1] = acc[mt][nt][1];
            dst[8 * Ss + 0] = acc[mt][nt][2];
            dst[8 * Ss + 1] = acc[mt][nt][3];
        }
    }
}

// ==================================================================================
// Kernel 3: softmax per row, faithful fp16 rounding at each op boundary
// ==================================================================================
__global__ __launch_bounds__(256) void softmax_kernel() {
    const int row  = blockIdx.x * 8 + (threadIdx.x >> 5);
    const int lane = threadIdx.x & 31;

    const float* srow = g_scores + (size_t)row * Ss;
    __half* arow = g_attn + (size_t)row * Ss;

    float l[8];
    float m = -1e30f;
#pragma unroll
    for (int i = 0; i < 8; i++) {
        float v = __half2float(__float2half(srow[lane + 32 * i])) * 0.015625f;
        l[i] = v;
        m = fmaxf(m, v);
    }
#pragma unroll
    for (int o = 16; o > 0; o >>= 1) m = fmaxf(m, __shfl_xor_sync(0xffffffffu, m, o));

    float e[8];
    float sum = 0.f;
#pragma unroll
    for (int i = 0; i < 8; i++) {
        float t = __half2float(__float2half(l[i] - m));
        e[i] = __half2float(__float2half(expf(t)));
        sum += e[i];
    }
#pragma unroll
    for (int o = 16; o > 0; o >>= 1) sum += __shfl_xor_sync(0xffffffffu, sum, o);

#pragma unroll
    for (int i = 0; i < 8; i++)
        arow[lane + 32 * i] = __float2half(e[i] / sum);
}

// ==================================================================================
// Kernel 4: SA = attn @ V via HMMA, cp.async 2-stage pipeline
//   grid: (BH, 2, 32)  block: 256 (8 warps, 2m x 4n, warp tile 64x32)
// ==================================================================================
__global__ __launch_bounds__(256) void av_mma_kernel() {
    extern __shared__ __half sma[];
    __half* As = sma;                    // [2][128*64]
    __half* Vs = sma + 2 * 128 * 64;     // [2][64*128]

    const int bh = blockIdx.x;
    const int m0 = blockIdx.y * 128;
    const int n0 = blockIdx.z * 128;
    const int tid = threadIdx.x, lane = tid & 31, warp = tid >> 5;
    const int wm = warp & 1;
    const int wn = warp >> 1;

    const __half* ab = g_attn + (size_t)bh * Ss * Ss;
    const __half* vb = g_v + (size_t)bh * Ss * Dd;

    float acc[4][4][4];
#pragma unroll
    for (int mt = 0; mt < 4; mt++)
#pragma unroll
        for (int nt = 0; nt < 4; nt++)
#pragma unroll
            for (int c = 0; c < 4; c++) acc[mt][nt][c] = 0.f;

    auto issue_loads = [&](int buf, int kk) {
        __half* Ab = As + buf * 128 * 64;
        __half* Vb = Vs + buf * 64 * 128;
#pragma unroll
        for (int i = 0; i < 4; i++) {
            int cid = tid + i * 256;
            int row = cid >> 3, c8 = cid & 7;
            int sw = (c8 ^ (row & 7)) << 3;
            cp16(Ab + row * 64 + sw, ab + (size_t)(m0 + row) * Ss + kk + c8 * 8);
        }
#pragma unroll
        for (int i = 0; i < 4; i++) {
            int cid = tid + i * 256;
            int row = cid >> 4, c = cid & 15;
            int sw = (c ^ (row & 7)) << 3;
            cp16(Vb + row * 128 + sw, vb + (size_t)(kk + row) * Dd + n0 + c * 8);
        }
        cp_commit();
    };

    issue_loads(0, 0);
    const int T = Ss / 64;   // 4
    for (int t = 0; t < T; t++) {
        if (t + 1 < T) {
            issue_loads((t + 1) & 1, (t + 1) * 64);
            cp_wait<1>();
        } else {
            cp_wait<0>();
        }
        __syncthreads();

        const __half* Ab = As + (t & 1) * 128 * 64;
        const __half* Vb = Vs + (t & 1) * 64 * 128;
#pragma unroll
        for (int ks = 0; ks < 4; ks++) {
            uint32_t a[4][4], b[4][2];
#pragma unroll
            for (int mt = 0; mt < 4; mt++) {
                int row = wm * 64 + mt * 16 + (lane & 15);
                int chk = ks * 2 + (lane >> 4);
                ldsm_x4(a[mt], Ab + row * 64 + ((chk ^ (row & 7)) << 3));
            }
#pragma unroll
            for (int nt = 0; nt < 4; nt++) {
                int row = ks * 16 + (lane & 15);
                int chk = wn * 4 + nt;
                ldsm_x2t(b[nt], Vb + row * 128 + ((chk ^ (row & 7)) << 3));
            }
#pragma unroll
            for (int mt = 0; mt < 4; mt++)
#pragma unroll
                for (int nt = 0; nt < 4; nt++)
                    mma_16816(acc[mt][nt], a[mt], b[nt]);
        }
        __syncthreads();
    }

#pragma unroll
    for (int mt = 0; mt < 4; mt++) {
#pragma unroll
        for (int nt = 0; nt < 4; nt++) {
            int r = m0 + wm * 64 + mt * 16 + (lane >> 2);
            int c = n0 + wn * 32 + nt * 8 + (lane & 3) * 2;
            __half* dst = g_sa + ((size_t)bh * Ss + r) * Dd + c;
            *(__half2*)dst = __floats2half2_rn(acc[mt][nt][0], acc[mt][nt][1]);
            *(__half2*)(dst + 8 * Dd) = __floats2half2_rn(acc[mt][nt][2], acc[mt][nt][3]);
        }
    }
}

// ==================================================================================
// Kernel 5: recompose2d gather + output projection via HMMA (2-pass w hi/lo)
//   grid: (B*S, 8)  block: 256 (8 warps = 4m x 2n, warp tile 32x32)
// ==================================================================================
__global__ __launch_bounds__(256) void out_mma_kernel(const float* __restrict__ w_out,
                                                      const float* __restrict__ b_out,
                                                      float* __restrict__ out) {
    __shared__ __align__(16) __half Ah[64 * XST];    // gathered SA [c][p] (exact fp16)
    __shared__ __align__(16) __half Whi2[64 * WST];  // [o][c]
    __shared__ __align__(16) __half Wlo2[64 * WST];

    const int bs  = blockIdx.x;
    const int p0  = blockIdx.y * 128;
    const int tid = threadIdx.x, lane = tid & 31, warp = tid >> 5;
    const int wm = warp >> 1;          // 0..3 -> m block of 32
    const int wn = warp & 1;           // 0..1 -> n block of 32
    const int b = bs >> 8, s = bs & 255;

    // gather SA (recompose2d) into [c][p]
#pragma unroll
    for (int i = 0; i < 32; i++) {
        int idx = tid + i * 256;           // 0..8191
        int c = idx >> 7, p = idx & 127;
        int pg = p0 + p;
        int h = pg >> 5, w = pg & 31;
        int head = ((h >> 4) * 2 + (w >> 4)) * 4 + (c >> 4);
        int d = (c & 15) * 256 + (h & 15) * 16 + (w & 15);
        Ah[c * XST + p] = g_sa[((size_t)(b * NHh + head) * Ss + s) * Dd + d];
    }
    // W split hi/lo
#pragma unroll
    for (int i = 0; i < 4; i++) {
        int cid = tid + i * 256;           // 0..1023 float4s
        int o = cid >> 4, e4 = (cid & 15) * 4;
        float4 v = *(const float4*)(w_out + o * 64 + e4);
        __half h0, l0, h1, l1, h2, l2, h3, l3;
        split_f32(v.x, h0, l0); split_f32(v.y, h1, l1);
        split_f32(v.z, h2, l2); split_f32(v.w, h3, l3);
        __half* dh = Whi2 + o * WST + e4;
        dh[0] = h0; dh[1] = h1; dh[2] = h2; dh[3] = h3;
        __half* dl = Wlo2 + o * WST + e4;
        dl[0] = l0; dl[1] = l1; dl[2] = l2; dl[3] = l3;
    }
    __syncthreads();

    float acc[2][4][4];
#pragma unroll
    for (int mt = 0; mt < 2; mt++)
#pragma unroll
        for (int nt = 0; nt < 4; nt++)
#pragma unroll
            for (int c = 0; c < 4; c++) acc[mt][nt][c] = 0.f;

    const int akrow = A_TRANS_KROW(lane);
    const int amoff = A_TRANS_MOFF(lane);
    const int bnrow = lane & 7;
    const int bkoff = ((lane >> 3) & 1) * 8;

#pragma unroll
    for (int pass = 0; pass < 2; pass++) {
        const __half* Wp = pass ? Wlo2 : Whi2;
#pragma unroll
        for (int ks = 0; ks < 4; ks++) {
            uint32_t a[2][4], bfr[4][2];
#pragma unroll
            for (int mt = 0; mt < 2; mt++)
                ldsm_x4t(a[mt], Ah + (ks * 16 + akrow) * XST
                                   + wm * 32 + mt * 16 + amoff);
#pragma unroll
            for (int nt = 0; nt < 4; nt++)
                ldsm_x2(bfr[nt], Wp + (wn * 32 + nt * 8 + bnrow) * WST
                                    + ks * 16 + bkoff);
#pragma unroll
            for (int mt = 0; mt < 2; mt++)
#pragma unroll
                for (int nt = 0; nt < 4; nt++)
                    mma_16816(acc[mt][nt], a[mt], bfr[nt]);
        }
    }

    // epilogue: out[bs][o][p] = acc + bias
#pragma unroll
    for (int mt = 0; mt < 2; mt++) {
        int r0 = wm * 32 + mt * 16 + (lane >> 2);
#pragma unroll
        for (int nt = 0; nt < 4; nt++) {
            int ob = wn * 32 + nt * 8 + (lane & 3) * 2;
#pragma unroll
            for (int c = 0; c < 4; c++) {
                int o  = ob + (c & 1);
                int rr = r0 + (c >> 1) * 8;
                out[((size_t)bs * 64 + o) * HWp + p0 + rr] = acc[mt][nt][c] + b_out[o];
            }
        }
    }
}

// ==================================================================================
extern "C" void kernel_launch(void* const* d_in, const int* in_sizes, int n_in,
                              void* d_out, int out_size) {
    const float* seq   = (const float*)d_in[0];
    const float* w_qkv = (const float*)d_in[1];
    const float* w_out = (const float*)d_in[2];
    const float* b_out = (const float*)d_in[3];
    float* out = (float*)d_out;

    const int qkv_smem = (2 * 64 * XST + 2 * 192 * WST) * (int)sizeof(__half);
    cudaFuncSetAttribute(qkv_mma_kernel, cudaFuncAttributeMaxDynamicSharedMemorySize,
                         qkv_smem);
    const int av_smem = (2 * 128 * 64 + 2 * 64 * 128) * (int)sizeof(__half);
    cudaFuncSetAttribute(av_mma_kernel, cudaFuncAttributeMaxDynamicSharedMemorySize,
                         av_smem);

    dim3 g1(Bb * Ss, 8);
    qkv_mma_kernel<<<g1, 256, qkv_smem>>>(seq, w_qkv);

    dim3 g2(BHh, 4, 4);
    scores_mma_kernel<<<g2, 128>>>();

    softmax_kernel<<<BHh * Ss / 8, 256>>>();

    dim3 g4(BHh, 2, 32);
    av_mma_kernel<<<g4, 256, av_smem>>>();

    dim3 g5(Bb * Ss, 8);
    out_mma_kernel<<<g5, 256>>>(w_out, b_out, out);
}

// round 6
// speedup vs baseline: 4.6894x; 1.0383x over previous
#include <cuda_runtime.h>
#include <cuda_fp16.h>
#include <cstdint>

// Problem constants (shapes are fixed by the dataset)
#define Bb   2
#define Ss   256
#define Ee   64
#define HWp  1024      // H*W = 32*32
#define CHh  4
#define NHh  16        // heads per batch = (XH*YH)*CH
#define BHh  32        // Bb*NHh
#define Dd   4096      // hd*hh*ww = 16*16*16

// -------------------- scratch (device globals; no allocation) --------------------
__device__ __half g_q[(size_t)BHh * Ss * Dd];      // 64 MB
__device__ __half g_k[(size_t)BHh * Ss * Dd];      // 64 MB
__device__ __half g_v[(size_t)BHh * Ss * Dd];      // 64 MB
__device__ float  g_scores[(size_t)BHh * Ss * Ss]; // 8 MB
__device__ __half g_attn[(size_t)BHh * Ss * Ss];   // 4 MB
__device__ __half g_sa[(size_t)BHh * Ss * Dd];     // 64 MB

// -------------------- mma / ldmatrix / cp.async helpers --------------------
__device__ __forceinline__ void mma_16816(float* c, const uint32_t* a, const uint32_t* b) {
    asm volatile(
        "mma.sync.aligned.m16n8k16.row.col.f32.f16.f16.f32 "
        "{%0,%1,%2,%3},{%4,%5,%6,%7},{%8,%9},{%0,%1,%2,%3};"
        : "+f"(c[0]), "+f"(c[1]), "+f"(c[2]), "+f"(c[3])
        : "r"(a[0]), "r"(a[1]), "r"(a[2]), "r"(a[3]), "r"(b[0]), "r"(b[1]));
}

__device__ __forceinline__ void ldsm_x4(uint32_t* r, const __half* p) {
    uint32_t addr = (uint32_t)__cvta_generic_to_shared(p);
    asm volatile("ldmatrix.sync.aligned.m8n8.x4.shared.b16 {%0,%1,%2,%3}, [%4];"
                 : "=r"(r[0]), "=r"(r[1]), "=r"(r[2]), "=r"(r[3]) : "r"(addr));
}
__device__ __forceinline__ void ldsm_x4t(uint32_t* r, const __half* p) {
    uint32_t addr = (uint32_t)__cvta_generic_to_shared(p);
    asm volatile("ldmatrix.sync.aligned.m8n8.x4.trans.shared.b16 {%0,%1,%2,%3}, [%4];"
                 : "=r"(r[0]), "=r"(r[1]), "=r"(r[2]), "=r"(r[3]) : "r"(addr));
}
__device__ __forceinline__ void ldsm_x2(uint32_t* r, const __half* p) {
    uint32_t addr = (uint32_t)__cvta_generic_to_shared(p);
    asm volatile("ldmatrix.sync.aligned.m8n8.x2.shared.b16 {%0,%1}, [%2];"
                 : "=r"(r[0]), "=r"(r[1]) : "r"(addr));
}

__device__ __forceinline__ void cp16(__half* smem, const __half* gmem) {
    uint32_t s = (uint32_t)__cvta_generic_to_shared(smem);
    asm volatile("cp.async.cg.shared.global [%0], [%1], 16;" :: "r"(s), "l"(gmem));
}
__device__ __forceinline__ void cp_commit() {
    asm volatile("cp.async.commit_group;");
}
template <int N>
__device__ __forceinline__ void cp_wait() {
    asm volatile("cp.async.wait_group %0;" :: "n"(N));
}

__device__ __forceinline__ void split_f32(float v, __half& hi, __half& lo) {
    hi = __float2half_rn(v);
    lo = __float2half_rn(v - __half2float(hi));
}

// A-fragment (m16k16, row-major A) from transposed smem storage S[k][m]
#define A_TRANS_KROW(lane)  (((lane) & 7) + (((lane) >> 4) << 3))
#define A_TRANS_MOFF(lane)  ((((lane) >> 3) & 1) << 3)

// ==================================================================================
// Kernel 1: QKV projection via HMMA with fp16 hi/lo split (3 passes)
//   grid: (B*S, 8)  block: 256 (8 warps = 2m x 4n, warp tile 64x48)
// ==================================================================================
#define XST 136   // X smem row stride (halves): 128 + 8 pad
#define WST 72    // W smem row stride (halves): 64 + 8 pad
#define OST 136   // out staging stride

__global__ __launch_bounds__(256) void qkv_mma_kernel(const float* __restrict__ seq,
                                                      const float* __restrict__ w_qkv) {
    extern __shared__ __half smq[];
    __half* Xhi = smq;                 // [64 e][136] (cols = p)
    __half* Xlo = Xhi + 64 * XST;
    __half* Whi = Xlo + 64 * XST;      // [192 o][72] (cols = e)
    __half* Wlo = Whi + 192 * WST;

    const int bs  = blockIdx.x;
    const int p0  = blockIdx.y * 128;
    const int tid = threadIdx.x, lane = tid & 31, warp = tid >> 5;
    const int wm = warp >> 2;
    const int wn = warp & 3;

    const float* src = seq + (size_t)bs * Ee * HWp + p0;
#pragma unroll
    for (int i = 0; i < 8; i++) {
        int cid = tid + i * 256;
        int e = cid >> 5, p4 = (cid & 31) * 4;
        float4 v = *(const float4*)(src + (size_t)e * HWp + p4);
        __half h0, l0, h1, l1, h2, l2, h3, l3;
        split_f32(v.x, h0, l0); split_f32(v.y, h1, l1);
        split_f32(v.z, h2, l2); split_f32(v.w, h3, l3);
        __half* dh = Xhi + e * XST + p4;
        dh[0] = h0; dh[1] = h1; dh[2] = h2; dh[3] = h3;
        __half* dl = Xlo + e * XST + p4;
        dl[0] = l0; dl[1] = l1; dl[2] = l2; dl[3] = l3;
    }
#pragma unroll
    for (int i = 0; i < 12; i++) {
        int cid = tid + i * 256;
        int o = cid >> 4, e4 = (cid & 15) * 4;
        float4 v = *(const float4*)(w_qkv + o * 64 + e4);
        __half h0, l0, h1, l1, h2, l2, h3, l3;
        split_f32(v.x, h0, l0); split_f32(v.y, h1, l1);
        split_f32(v.z, h2, l2); split_f32(v.w, h3, l3);
        __half* dh = Whi + o * WST + e4;
        dh[0] = h0; dh[1] = h1; dh[2] = h2; dh[3] = h3;
        __half* dl = Wlo + o * WST + e4;
        dl[0] = l0; dl[1] = l1; dl[2] = l2; dl[3] = l3;
    }
    __syncthreads();

    float acc[4][6][4];
#pragma unroll
    for (int mt = 0; mt < 4; mt++)
#pragma unroll
        for (int nt = 0; nt < 6; nt++)
#pragma unroll
            for (int c = 0; c < 4; c++) acc[mt][nt][c] = 0.f;

    const int akrow = A_TRANS_KROW(lane);
    const int amoff = A_TRANS_MOFF(lane);
    const int bnrow = lane & 7;
    const int bkoff = ((lane >> 3) & 1) * 8;

#pragma unroll
    for (int pass = 0; pass < 3; pass++) {
        const __half* Xp = (pass == 2) ? Xlo : Xhi;
        const __half* Wp = (pass == 1) ? Wlo : Whi;
#pragma unroll
        for (int ks = 0; ks < 4; ks++) {
            uint32_t a[4][4], b[6][2];
#pragma unroll
            for (int mt = 0; mt < 4; mt++)
                ldsm_x4t(a[mt], Xp + (ks * 16 + akrow) * XST
                                   + wm * 64 + mt * 16 + amoff);
#pragma unroll
            for (int nt = 0; nt < 6; nt++)
                ldsm_x2(b[nt], Wp + (wn * 48 + nt * 8 + bnrow) * WST
                                  + ks * 16 + bkoff);
#pragma unroll
            for (int mt = 0; mt < 4; mt++)
#pragma unroll
                for (int nt = 0; nt < 6; nt++)
                    mma_16816(acc[mt][nt], a[mt], b[nt]);
        }
    }

    __syncthreads();
    __half* OutS = smq;                    // [192][OST]
#pragma unroll
    for (int mt = 0; mt < 4; mt++) {
        int r0 = wm * 64 + mt * 16 + (lane >> 2);
#pragma unroll
        for (int nt = 0; nt < 6; nt++) {
            int ob = wn * 48 + nt * 8 + (lane & 3) * 2;
#pragma unroll
            for (int c = 0; c < 4; c++) {
                int o  = ob + (c & 1);
                int pl = r0 + (c >> 1) * 8;
                OutS[o * OST + pl] = __float2half(acc[mt][nt][c]);
            }
        }
    }
    __syncthreads();

    const int b = bs >> 8, s = bs & 255;
    const int h_base = blockIdx.y * 4;
#pragma unroll
    for (int it = 0; it < 6; it++) {
        int seg = tid + it * 256;
        int o   = seg >> 3;
        int sub = seg & 7;
        int hl  = sub >> 1;
        int sy  = sub & 1;
        int h   = h_base + hl;
        int sx = h >> 4, ii = h & 15;
        int sp = o >> 6, ch = (o >> 4) & 3, dc = o & 15;
        int head = (sx * 2 + sy) * 4 + ch;
        __half* dst = (sp == 0) ? g_q : (sp == 1) ? g_k : g_v;
        size_t di = ((size_t)(b * NHh + head) * Ss + s) * Dd + dc * 256 + ii * 16;
        const uint4* sp4 = (const uint4*)(OutS + o * OST + hl * 32 + sy * 16);
        *(uint4*)(dst + di)     = sp4[0];
        *(uint4*)(dst + di + 8) = sp4[1];
    }
}

// ==================================================================================
// Kernel 2: scores = Q @ K^T via HMMA, 64x64 tiles, cp.async 2-stage pipeline
//   grid: (BH, 4, 4)  block: 128 (4 warps, 2m x 2n, warp tile 32x32)
// ==================================================================================
__global__ __launch_bounds__(128) void scores_mma_kernel() {
    __shared__ __align__(16) __half Qs[2][64 * 64];
    __shared__ __align__(16) __half Ks[2][64 * 64];

    const int bh = blockIdx.x;
    const int m0 = blockIdx.y * 64;
    const int n0 = blockIdx.z * 64;
    const int tid = threadIdx.x, lane = tid & 31, warp = tid >> 5;
    const int wm = warp >> 1;   // 0..1
    const int wn = warp & 1;    // 0..1

    const __half* qb = g_q + (size_t)bh * Ss * Dd;
    const __half* kb = g_k + (size_t)bh * Ss * Dd;

    float acc[2][4][4];
#pragma unroll
    for (int mt = 0; mt < 2; mt++)
#pragma unroll
        for (int nt = 0; nt < 4; nt++)
#pragma unroll
            for (int c = 0; c < 4; c++) acc[mt][nt][c] = 0.f;

    auto issue_loads = [&](int buf, int kk) {
#pragma unroll
        for (int i = 0; i < 4; i++) {
            int cid = tid + i * 128;          // 0..511
            int row = cid >> 3, c8 = cid & 7;
            int sw = (c8 ^ (row & 7)) << 3;
            cp16(Qs[buf] + row * 64 + sw, qb + (size_t)(m0 + row) * Dd + kk + c8 * 8);
            cp16(Ks[buf] + row * 64 + sw, kb + (size_t)(n0 + row) * Dd + kk + c8 * 8);
        }
        cp_commit();
    };

    issue_loads(0, 0);
    const int T = Dd / 64;   // 64
    for (int t = 0; t < T; t++) {
        if (t + 1 < T) {
            issue_loads((t + 1) & 1, (t + 1) * 64);
            cp_wait<1>();
        } else {
            cp_wait<0>();
        }
        __syncthreads();

        const __half* Qb = Qs[t & 1];
        const __half* Kb = Ks[t & 1];
#pragma unroll
        for (int ks = 0; ks < 4; ks++) {
            uint32_t a[2][4], b[4][2];
#pragma unroll
            for (int mt = 0; mt < 2; mt++) {
                int row = wm * 32 + mt * 16 + (lane & 15);
                int chk = ks * 2 + (lane >> 4);
                ldsm_x4(a[mt], Qb + row * 64 + ((chk ^ (row & 7)) << 3));
            }
#pragma unroll
            for (int nt = 0; nt < 4; nt++) {
                int row = wn * 32 + nt * 8 + (lane & 7);
                int chk = ks * 2 + ((lane >> 3) & 1);
                ldsm_x2(b[nt], Kb + row * 64 + ((chk ^ (row & 7)) << 3));
            }
#pragma unroll
            for (int mt = 0; mt < 2; mt++)
#pragma unroll
                for (int nt = 0; nt < 4; nt++)
                    mma_16816(acc[mt][nt], a[mt], b[nt]);
        }
        __syncthreads();
    }

#pragma unroll
    for (int mt = 0; mt < 2; mt++) {
#pragma unroll
        for (int nt = 0; nt < 4; nt++) {
            int r = m0 + wm * 32 + mt * 16 + (lane >> 2);
            int c = n0 + wn * 32 + nt * 8 + (lane & 3) * 2;
            float* dst = g_scores + ((size_t)bh * Ss + r) * Ss + c;
            dst[0] = acc[mt][nt][0];
            dst[1] = acc[mt][nt][1];
            dst[8 * Ss + 0] = acc[mt][nt][2];
            dst[8 * Ss + 1] = acc[mt][nt][3];
        }
    }
}

// ==================================================================================
// Kernel 3: softmax per row, faithful fp16 rounding at each op boundary
// ==================================================================================
__global__ __launch_bounds__(256) void softmax_kernel() {
    const int row  = blockIdx.x * 8 + (threadIdx.x >> 5);
    const int lane = threadIdx.x & 31;

    const float* srow = g_scores + (size_t)row * Ss;
    __half* arow = g_attn + (size_t)row * Ss;

    float l[8];
    float m = -1e30f;
#pragma unroll
    for (int i = 0; i < 8; i++) {
        float v = __half2float(__float2half(srow[lane + 32 * i])) * 0.015625f;
        l[i] = v;
        m = fmaxf(m, v);
    }
#pragma unroll
    for (int o = 16; o > 0; o >>= 1) m = fmaxf(m, __shfl_xor_sync(0xffffffffu, m, o));

    float e[8];
    float sum = 0.f;
#pragma unroll
    for (int i = 0; i < 8; i++) {
        float t = __half2float(__float2half(l[i] - m));
        e[i] = __half2float(__float2half(expf(t)));
        sum += e[i];
    }
#pragma unroll
    for (int o = 16; o > 0; o >>= 1) sum += __shfl_xor_sync(0xffffffffu, sum, o);

#pragma unroll
    for (int i = 0; i < 8; i++)
        arow[lane + 32 * i] = __float2half(e[i] / sum);
}

// ==================================================================================
// Kernel 4: SA = attn @ V via HMMA, cp.async 2-stage, 2 CTAs/SM forced
//   grid: (BH, 2, 32)  block: 256 (8 warps, 2m x 4n, warp tile 64x32)
// ==================================================================================
__global__ __launch_bounds__(256, 2) void av_mma_kernel() {
    extern __shared__ __half sma[];
    __half* As = sma;                    // [2][128*64]
    __half* Vs = sma + 2 * 128 * 64;     // [2][64*128]

    const int bh = blockIdx.x;
    const int m0 = blockIdx.y * 128;
    const int n0 = blockIdx.z * 128;
    const int tid = threadIdx.x, lane = tid & 31, warp = tid >> 5;
    const int wm = warp & 1;
    const int wn = warp >> 1;

    const __half* ab = g_attn + (size_t)bh * Ss * Ss;
    const __half* vb = g_v + (size_t)bh * Ss * Dd;

    float acc[4][4][4];
#pragma unroll
    for (int mt = 0; mt < 4; mt++)
#pragma unroll
        for (int nt = 0; nt < 4; nt++)
#pragma unroll
            for (int c = 0; c < 4; c++) acc[mt][nt][c] = 0.f;

    auto issue_loads = [&](int buf, int kk) {
        __half* Ab = As + buf * 128 * 64;
        __half* Vb = Vs + buf * 64 * 128;
#pragma unroll
        for (int i = 0; i < 4; i++) {
            int cid = tid + i * 256;
            int row = cid >> 3, c8 = cid & 7;
            int sw = (c8 ^ (row & 7)) << 3;
            cp16(Ab + row * 64 + sw, ab + (size_t)(m0 + row) * Ss + kk + c8 * 8);
        }
#pragma unroll
        for (int i = 0; i < 4; i++) {
            int cid = tid + i * 256;
            int row = cid >> 4, c = cid & 15;
            int sw = (c ^ (row & 7)) << 3;
            cp16(Vb + row * 128 + sw, vb + (size_t)(kk + row) * Dd + n0 + c * 8);
        }
        cp_commit();
    };

    issue_loads(0, 0);
    const int T = Ss / 64;   // 4
    for (int t = 0; t < T; t++) {
        if (t + 1 < T) {
            issue_loads((t + 1) & 1, (t + 1) * 64);
            cp_wait<1>();
        } else {
            cp_wait<0>();
        }
        __syncthreads();

        const __half* Ab = As + (t & 1) * 128 * 64;
        const __half* Vb = Vs + (t & 1) * 64 * 128;
#pragma unroll
        for (int ks = 0; ks < 4; ks++) {
            uint32_t a[4][4], b[4][2];
#pragma unroll
            for (int mt = 0; mt < 4; mt++) {
                int row = wm * 64 + mt * 16 + (lane & 15);
                int chk = ks * 2 + (lane >> 4);
                ldsm_x4(a[mt], Ab + row * 64 + ((chk ^ (row & 7)) << 3));
            }
#pragma unroll
            for (int np = 0; np < 4; np += 2) {
                uint32_t r4[4];
                int row = ks * 16 + (lane & 15);
                int chk = wn * 4 + np + (lane >> 4);
                ldsm_x4t(r4, Vb + row * 128 + ((chk ^ (row & 7)) << 3));
                b[np][0] = r4[0]; b[np][1] = r4[1];
                b[np + 1][0] = r4[2]; b[np + 1][1] = r4[3];
            }
#pragma unroll
            for (int mt = 0; mt < 4; mt++)
#pragma unroll
                for (int nt = 0; nt < 4; nt++)
                    mma_16816(acc[mt][nt], a[mt], b[nt]);
        }
        __syncthreads();
    }

#pragma unroll
    for (int mt = 0; mt < 4; mt++) {
#pragma unroll
        for (int nt = 0; nt < 4; nt++) {
            int r = m0 + wm * 64 + mt * 16 + (lane >> 2);
            int c = n0 + wn * 32 + nt * 8 + (lane & 3) * 2;
            __half* dst = g_sa + ((size_t)bh * Ss + r) * Dd + c;
            *(__half2*)dst = __floats2half2_rn(acc[mt][nt][0], acc[mt][nt][1]);
            *(__half2*)(dst + 8 * Dd) = __floats2half2_rn(acc[mt][nt][2], acc[mt][nt][3]);
        }
    }
}

// ==================================================================================
// Kernel 5: recompose2d gather + output projection via HMMA (2-pass w hi/lo)
// ==================================================================================
__global__ __launch_bounds__(256) void out_mma_kernel(const float* __restrict__ w_out,
                                                      const float* __restrict__ b_out,
                                                      float* __restrict__ out) {
    __shared__ __align__(16) __half Ah[64 * XST];
    __shared__ __align__(16) __half Whi2[64 * WST];
    __shared__ __align__(16) __half Wlo2[64 * WST];

    const int bs  = blockIdx.x;
    const int p0  = blockIdx.y * 128;
    const int tid = threadIdx.x, lane = tid & 31, warp = tid >> 5;
    const int wm = warp >> 1;
    const int wn = warp & 1;
    const int b = bs >> 8, s = bs & 255;

#pragma unroll
    for (int i = 0; i < 32; i++) {
        int idx = tid + i * 256;
        int c = idx >> 7, p = idx & 127;
        int pg = p0 + p;
        int h = pg >> 5, w = pg & 31;
        int head = ((h >> 4) * 2 + (w >> 4)) * 4 + (c >> 4);
        int d = (c & 15) * 256 + (h & 15) * 16 + (w & 15);
        Ah[c * XST + p] = g_sa[((size_t)(b * NHh + head) * Ss + s) * Dd + d];
    }
#pragma unroll
    for (int i = 0; i < 4; i++) {
        int cid = tid + i * 256;
        int o = cid >> 4, e4 = (cid & 15) * 4;
        float4 v = *(const float4*)(w_out + o * 64 + e4);
        __half h0, l0, h1, l1, h2, l2, h3, l3;
        split_f32(v.x, h0, l0); split_f32(v.y, h1, l1);
        split_f32(v.z, h2, l2); split_f32(v.w, h3, l3);
        __half* dh = Whi2 + o * WST + e4;
        dh[0] = h0; dh[1] = h1; dh[2] = h2; dh[3] = h3;
        __half* dl = Wlo2 + o * WST + e4;
        dl[0] = l0; dl[1] = l1; dl[2] = l2; dl[3] = l3;
    }
    __syncthreads();

    float acc[2][4][4];
#pragma unroll
    for (int mt = 0; mt < 2; mt++)
#pragma unroll
        for (int nt = 0; nt < 4; nt++)
#pragma unroll
            for (int c = 0; c < 4; c++) acc[mt][nt][c] = 0.f;

    const int akrow = A_TRANS_KROW(lane);
    const int amoff = A_TRANS_MOFF(lane);
    const int bnrow = lane & 7;
    const int bkoff = ((lane >> 3) & 1) * 8;

#pragma unroll
    for (int pass = 0; pass < 2; pass++) {
        const __half* Wp = pass ? Wlo2 : Whi2;
#pragma unroll
        for (int ks = 0; ks < 4; ks++) {
            uint32_t a[2][4], bfr[4][2];
#pragma unroll
            for (int mt = 0; mt < 2; mt++)
                ldsm_x4t(a[mt], Ah + (ks * 16 + akrow) * XST
                                   + wm * 32 + mt * 16 + amoff);
#pragma unroll
            for (int nt = 0; nt < 4; nt++)
                ldsm_x2(bfr[nt], Wp + (wn * 32 + nt * 8 + bnrow) * WST
                                    + ks * 16 + bkoff);
#pragma unroll
            for (int mt = 0; mt < 2; mt++)
#pragma unroll
                for (int nt = 0; nt < 4; nt++)
                    mma_16816(acc[mt][nt], a[mt], bfr[nt]);
        }
    }

#pragma unroll
    for (int mt = 0; mt < 2; mt++) {
        int r0 = wm * 32 + mt * 16 + (lane >> 2);
#pragma unroll
        for (int nt = 0; nt < 4; nt++) {
            int ob = wn * 32 + nt * 8 + (lane & 3) * 2;
#pragma unroll
            for (int c = 0; c < 4; c++) {
                int o  = ob + (c & 1);
                int rr = r0 + (c >> 1) * 8;
                out[((size_t)bs * 64 + o) * HWp + p0 + rr] = acc[mt][nt][c] + b_out[o];
            }
        }
    }
}

// ==================================================================================
extern "C" void kernel_launch(void* const* d_in, const int* in_sizes, int n_in,
                              void* d_out, int out_size) {
    const float* seq   = (const float*)d_in[0];
    const float* w_qkv = (const float*)d_in[1];
    const float* w_out = (const float*)d_in[2];
    const float* b_out = (const float*)d_in[3];
    float* out = (float*)d_out;

    const int qkv_smem = (2 * 64 * XST + 2 * 192 * WST) * (int)sizeof(__half);
    cudaFuncSetAttribute(qkv_mma_kernel, cudaFuncAttributeMaxDynamicSharedMemorySize,
                         qkv_smem);
    const int av_smem = (2 * 128 * 64 + 2 * 64 * 128) * (int)sizeof(__half);
    cudaFuncSetAttribute(av_mma_kernel, cudaFuncAttributeMaxDynamicSharedMemorySize,
                         av_smem);
    cudaFuncSetAttribute(av_mma_kernel, cudaFuncAttributePreferredSharedMemoryCarveout,
                         100);

    dim3 g1(Bb * Ss, 8);
    qkv_mma_kernel<<<g1, 256, qkv_smem>>>(seq, w_qkv);

    dim3 g2(BHh, 4, 4);
    scores_mma_kernel<<<g2, 128>>>();

    softmax_kernel<<<BHh * Ss / 8, 256>>>();

    dim3 g4(BHh, 2, 32);
    av_mma_kernel<<<g4, 256, av_smem>>>();

    dim3 g5(Bb * Ss, 8);
    out_mma_kernel<<<g5, 256>>>(w_out, b_out, out);
}